// round 1
// baseline (speedup 1.0000x reference)
#include <cuda_runtime.h>
#include <math.h>

#define N_TOK 4096
#define DDIM  512
#define KEEP  2048

// Scratch (device globals: allocation-free per harness rules)
__device__ float g_q[N_TOK * DDIM];
__device__ float g_k[N_TOK * DDIM];
__device__ float g_v[N_TOK * DDIM];
__device__ float g_score[(size_t)N_TOK * N_TOK];

// ---------------------------------------------------------------------------
// Generic fp32 register-tiled GEMM: C[M,N] = scale * (A[M,K] @ B[K,N]) (+bias)
// A row-major lda, B row-major ldb, C row-major ldc. All tile dims divide
// problem dims exactly (4096/512 vs 128/64), so no bounds checks.
// ---------------------------------------------------------------------------
template<int BM, int BN, int BK, int TM, int TN, bool BIAS>
__global__ void __launch_bounds__((BM/TM)*(BN/TN))
sgemm_kernel(const float* __restrict__ A, int lda,
             const float* __restrict__ B, int ldb,
             float* __restrict__ C, int ldc,
             int K, const float* __restrict__ bias, float scale)
{
    constexpr int TX = BN / TN;
    constexpr int TY = BM / TM;
    constexpr int THREADS = TX * TY;

    __shared__ float As[BK][BM];   // A tile transposed: As[k][m]
    __shared__ float Bs[BK][BN];

    const int tid = threadIdx.x;
    const int tx = tid % TX;
    const int ty = tid / TX;

    A += (size_t)blockIdx.y * BM * lda;
    B += (size_t)blockIdx.x * BN;
    C += (size_t)blockIdx.y * BM * ldc + (size_t)blockIdx.x * BN;

    float acc[TM][TN] = {};

    for (int k0 = 0; k0 < K; k0 += BK) {
        // A tile: BM x BK, float4 along K, store transposed
        #pragma unroll
        for (int i = tid; i < BM * BK / 4; i += THREADS) {
            const int r  = i / (BK / 4);
            const int c4 = i % (BK / 4);
            float4 v = *reinterpret_cast<const float4*>(A + (size_t)r * lda + k0 + c4 * 4);
            As[c4 * 4 + 0][r] = v.x;
            As[c4 * 4 + 1][r] = v.y;
            As[c4 * 4 + 2][r] = v.z;
            As[c4 * 4 + 3][r] = v.w;
        }
        // B tile: BK x BN, float4 contiguous
        #pragma unroll
        for (int i = tid; i < BK * BN / 4; i += THREADS) {
            const int r  = i / (BN / 4);
            const int c4 = i % (BN / 4);
            *reinterpret_cast<float4*>(&Bs[r][c4 * 4]) =
                *reinterpret_cast<const float4*>(B + (size_t)(k0 + r) * ldb + c4 * 4);
        }
        __syncthreads();

        #pragma unroll
        for (int k = 0; k < BK; ++k) {
            float ar[TM], br[TN];
            #pragma unroll
            for (int i = 0; i < TM; i += 4)
                *reinterpret_cast<float4*>(&ar[i]) =
                    *reinterpret_cast<const float4*>(&As[k][ty * TM + i]);
            #pragma unroll
            for (int j = 0; j < TN; j += 4)
                *reinterpret_cast<float4*>(&br[j]) =
                    *reinterpret_cast<const float4*>(&Bs[k][tx * TN + j]);
            #pragma unroll
            for (int i = 0; i < TM; ++i)
                #pragma unroll
                for (int j = 0; j < TN; ++j)
                    acc[i][j] += ar[i] * br[j];
        }
        __syncthreads();
    }

    #pragma unroll
    for (int i = 0; i < TM; ++i) {
        #pragma unroll
        for (int j = 0; j < TN; j += 4) {
            float4 o;
            o.x = acc[i][j + 0] * scale;
            o.y = acc[i][j + 1] * scale;
            o.z = acc[i][j + 2] * scale;
            o.w = acc[i][j + 3] * scale;
            if (BIAS) {
                const int cb = blockIdx.x * BN + tx * TN + j;
                o.x += bias[cb + 0];
                o.y += bias[cb + 1];
                o.z += bias[cb + 2];
                o.w += bias[cb + 3];
            }
            *reinterpret_cast<float4*>(C + (size_t)(ty * TM + i) * ldc + tx * TN + j) = o;
        }
    }
}

// ---------------------------------------------------------------------------
// Per-row exact top-k threshold (2048th largest of 4096) + masked softmax.
// One block of 1024 threads per row. Bitonic sort of a row copy in smem
// (ascending), thr = s[N - KEEP] (smallest of the top KEEP = topv[:,-1]).
// Mask: strict > thr, else 0. Softmax over the full masked row (zeros incl.)
// In-place: score row -> attn row.
// ---------------------------------------------------------------------------
__global__ void __launch_bounds__(1024)
topk_softmax_kernel(float* __restrict__ score)
{
    __shared__ float s[N_TOK];
    __shared__ float rmax[32];
    __shared__ float rsum[32];

    float* row = score + (size_t)blockIdx.x * N_TOK;
    const int tid = threadIdx.x;

    float orig[4];
    #pragma unroll
    for (int c = 0; c < 4; ++c) {
        orig[c] = row[tid + c * 1024];
        s[tid + c * 1024] = orig[c];
    }
    __syncthreads();

    // Bitonic sort, ascending. 2048 disjoint pairs per stage, 2 per thread.
    for (int kk = 2; kk <= N_TOK; kk <<= 1) {
        for (int j = kk >> 1; j > 0; j >>= 1) {
            #pragma unroll
            for (int t0 = 0; t0 < 2; ++t0) {
                const int t = tid + t0 * 1024;
                const int i = ((t & ~(j - 1)) << 1) | (t & (j - 1));
                const int l = i | j;
                const bool up = ((i & kk) == 0);
                const float a = s[i], b = s[l];
                if ((a > b) == up) { s[i] = b; s[l] = a; }
            }
            __syncthreads();
        }
    }

    const float thr = s[N_TOK - KEEP];

    // masked values + row max (zeros are present so max >= 0 anyway)
    float m[4];
    float lmax = 0.0f;
    #pragma unroll
    for (int c = 0; c < 4; ++c) {
        m[c] = (orig[c] > thr) ? orig[c] : 0.0f;
        lmax = fmaxf(lmax, m[c]);
    }
    #pragma unroll
    for (int o = 16; o; o >>= 1)
        lmax = fmaxf(lmax, __shfl_xor_sync(0xffffffffu, lmax, o));
    if ((tid & 31) == 0) rmax[tid >> 5] = lmax;
    __syncthreads();
    float gmax;
    {
        float v = rmax[tid & 31];
        #pragma unroll
        for (int o = 16; o; o >>= 1)
            v = fmaxf(v, __shfl_xor_sync(0xffffffffu, v, o));
        gmax = v;
    }

    float e[4];
    float lsum = 0.0f;
    #pragma unroll
    for (int c = 0; c < 4; ++c) {
        e[c] = expf(m[c] - gmax);
        lsum += e[c];
    }
    #pragma unroll
    for (int o = 16; o; o >>= 1)
        lsum += __shfl_xor_sync(0xffffffffu, lsum, o);
    if ((tid & 31) == 0) rsum[tid >> 5] = lsum;
    __syncthreads();
    float gsum;
    {
        float v = rsum[tid & 31];
        #pragma unroll
        for (int o = 16; o; o >>= 1)
            v += __shfl_xor_sync(0xffffffffu, v, o);
        gsum = v;
    }

    const float inv = 1.0f / gsum;
    #pragma unroll
    for (int c = 0; c < 4; ++c)
        row[tid + c * 1024] = e[c] * inv;
}

// ---------------------------------------------------------------------------
extern "C" void kernel_launch(void* const* d_in, const int* in_sizes, int n_in,
                              void* d_out, int out_size)
{
    const float* x  = (const float*)d_in[0];
    const float* Wq = (const float*)d_in[1];
    const float* bq = (const float*)d_in[2];
    const float* Wk = (const float*)d_in[3];
    const float* bk = (const float*)d_in[4];
    const float* Wv = (const float*)d_in[5];
    const float* bv = (const float*)d_in[6];
    float* out = (float*)d_out;

    float *q, *k, *v, *score;
    cudaGetSymbolAddress((void**)&q,     g_q);
    cudaGetSymbolAddress((void**)&k,     g_k);
    cudaGetSymbolAddress((void**)&v,     g_v);
    cudaGetSymbolAddress((void**)&score, g_score);

    const float inv_sqrt_d = 1.0f / sqrtf((float)DDIM);

    // QKV projections: M=4096, N=512, K=512
    {
        dim3 grid(DDIM / 128, N_TOK / 128);
        sgemm_kernel<128,128,8,8,8,true><<<grid, 256>>>(x, DDIM, Wq, DDIM, q, DDIM, DDIM, bq, 1.0f);
        sgemm_kernel<128,128,8,8,8,true><<<grid, 256>>>(x, DDIM, Wk, DDIM, k, DDIM, DDIM, bk, 1.0f);
        sgemm_kernel<128,128,8,8,8,true><<<grid, 256>>>(x, DDIM, Wv, DDIM, v, DDIM, DDIM, bv, 1.0f);
    }

    // Score: q [4096,512] @ reshape(k,(512,4096)) [ldb=4096], scaled
    {
        dim3 grid(N_TOK / 128, N_TOK / 128);
        sgemm_kernel<128,128,8,8,8,false><<<grid, 256>>>(q, DDIM, k, N_TOK, score, N_TOK,
                                                         DDIM, nullptr, inv_sqrt_d);
    }

    // Exact top-k threshold + masked softmax (in-place)
    topk_softmax_kernel<<<N_TOK, 1024>>>(score);

    // Context: attn [4096,4096] @ v [4096,512]
    {
        dim3 grid(DDIM / 64, N_TOK / 128);
        sgemm_kernel<128,64,8,8,4,false><<<grid, 256>>>(score, N_TOK, v, DDIM, out, DDIM,
                                                        N_TOK, nullptr, 1.0f);
    }
}

// round 3
// speedup vs baseline: 1.2133x; 1.2133x over previous
#include <cuda_runtime.h>
#include <cstdint>
#include <math.h>

#define N_TOK 4096
#define DDIM  512
#define KEEP  2048

// ---------------- device scratch (allocation-free) ----------------
__device__ float g_q [N_TOK * DDIM];
__device__ float g_k [N_TOK * DDIM];
__device__ float g_v [N_TOK * DDIM];
__device__ float g_kT[N_TOK * DDIM];
__device__ float g_vT[N_TOK * DDIM];
__device__ float g_WT[3][DDIM * DDIM];
__device__ float g_score[(size_t)N_TOK * N_TOK];
__device__ float g_part[4][N_TOK * DDIM];

// ---------------- helpers ----------------
__device__ __forceinline__ uint32_t smem_u32(const void* p) {
    uint32_t a;
    asm("{ .reg .u64 t; cvta.to.shared.u64 t, %1; cvt.u32.u64 %0, t; }"
        : "=r"(a) : "l"(p));
    return a;
}
__device__ __forceinline__ uint32_t tf32_of(float f) {
    uint32_t u;
    asm("cvt.rna.tf32.f32 %0, %1;" : "=r"(u) : "f"(f));
    return u;
}

#define CP16(dst, src) \
    asm volatile("cp.async.cg.shared.global [%0], [%1], 16;" :: "r"(dst), "l"(src) : "memory")
#define CP_COMMIT() asm volatile("cp.async.commit_group;" ::: "memory")
#define CP_WAIT1()  asm volatile("cp.async.wait_group 1;" ::: "memory")
#define CP_WAIT0()  asm volatile("cp.async.wait_group 0;" ::: "memory")

// m16n8k8 tf32 MMA, D += A*B  (row.col)
#define MMA8(cc, a, b)                                                          \
    asm volatile("mma.sync.aligned.m16n8k8.row.col.f32.tf32.tf32.f32 "          \
        "{%0,%1,%2,%3}, {%4,%5,%6,%7}, {%8,%9}, {%0,%1,%2,%3};"                 \
        : "+f"((cc)[0]), "+f"((cc)[1]), "+f"((cc)[2]), "+f"((cc)[3])            \
        : "r"((a)[0]), "r"((a)[1]), "r"((a)[2]), "r"((a)[3]),                   \
          "r"((b)[0]), "r"((b)[1]))

// ---------------------------------------------------------------------------
// 3xTF32 mma.sync GEMM: C[M,N] = scale*(A @ B^T) (+bias)
// A [M,K] row-major (lda), B [N,K] row-major (ldb), C row-major (ldc).
// Block 128x128, BK=32, 256 threads, 8 warps in 2(m) x 4(n), warp tile 64x32.
// Smem: double-buffered raw fp32 tiles As[128][36] + Bs[128][36] (pad 36:
// fragment LDS bank = (4g + tig + const) % 32 -> conflict-free).
// ---------------------------------------------------------------------------
#define TILE_F   (128 * 36)               // floats per tile
#define STAGE_B  (2 * TILE_F * 4)         // bytes per stage (A+B)
#define GEMM_SMEM_BYTES (2 * STAGE_B)     // 73728

template<bool BIAS>
__global__ void __launch_bounds__(256, 1)
mma3t_kernel(const float* __restrict__ A, int lda,
             const float* __restrict__ B, int ldb,
             float* __restrict__ C, int ldc,
             int K, const float* __restrict__ bias, float scale)
{
    extern __shared__ char sm[];
    const uint32_t smb = smem_u32(sm);

    const int tid  = threadIdx.x;
    const int w    = tid >> 5;
    const int lane = tid & 31;
    const int wm   = w & 1;           // 0..1
    const int wn   = w >> 1;          // 0..3
    const int g    = lane >> 2;       // 0..7
    const int tig  = lane & 3;        // 0..3

    // global loader mapping: thread t -> row t>>1, 16-float half (t&1)
    const int lrow = tid >> 1;
    const int lcol = (tid & 1) * 16;
    const float* Ap = A + (size_t)(blockIdx.y * 128 + lrow) * lda + lcol;
    const float* Bp = B + (size_t)(blockIdx.x * 128 + lrow) * ldb + lcol;
    const uint32_t sAo = (uint32_t)(lrow * 36 + lcol) * 4;           // byte off in tile
    const uint32_t sBo = sAo + TILE_F * 4;

    float c[4][4][4] = {};

    const int nT = K >> 5;

    // prologue: stage 0 load
    {
        const uint32_t st = smb;
        #pragma unroll
        for (int j = 0; j < 4; ++j) {
            CP16(st + sAo + j * 16, Ap + j * 4);
            CP16(st + sBo + j * 16, Bp + j * 4);
        }
        CP_COMMIT();
    }

    for (int kt = 0; kt < nT; ++kt) {
        if (kt + 1 < nT) {
            const uint32_t st = smb + ((kt + 1) & 1) * STAGE_B;
            const float* a1 = Ap + (kt + 1) * 32;
            const float* b1 = Bp + (kt + 1) * 32;
            #pragma unroll
            for (int j = 0; j < 4; ++j) {
                CP16(st + sAo + j * 16, a1 + j * 4);
                CP16(st + sBo + j * 16, b1 + j * 4);
            }
            CP_COMMIT();
            CP_WAIT1();
        } else {
            CP_WAIT0();
        }
        __syncthreads();

        const float* As = (const float*)(sm + (kt & 1) * STAGE_B);
        const float* Bs = As + TILE_F;

        #pragma unroll
        for (int ks = 0; ks < 4; ++ks) {
            const int kb = ks * 8;

            uint32_t ah[4][4], al[4][4];
            #pragma unroll
            for (int mi = 0; mi < 4; ++mi) {
                const int r0 = wm * 64 + mi * 16 + g;
                const float f0 = As[r0 * 36 + kb + tig];
                const float f1 = As[(r0 + 8) * 36 + kb + tig];
                const float f2 = As[r0 * 36 + kb + tig + 4];
                const float f3 = As[(r0 + 8) * 36 + kb + tig + 4];
                ah[mi][0] = tf32_of(f0); al[mi][0] = tf32_of(f0 - __uint_as_float(ah[mi][0]));
                ah[mi][1] = tf32_of(f1); al[mi][1] = tf32_of(f1 - __uint_as_float(ah[mi][1]));
                ah[mi][2] = tf32_of(f2); al[mi][2] = tf32_of(f2 - __uint_as_float(ah[mi][2]));
                ah[mi][3] = tf32_of(f3); al[mi][3] = tf32_of(f3 - __uint_as_float(ah[mi][3]));
            }
            uint32_t bh[4][2], bl[4][2];
            #pragma unroll
            for (int ni = 0; ni < 4; ++ni) {
                const int rb = wn * 32 + ni * 8 + g;
                const float f0 = Bs[rb * 36 + kb + tig];
                const float f1 = Bs[rb * 36 + kb + tig + 4];
                bh[ni][0] = tf32_of(f0); bl[ni][0] = tf32_of(f0 - __uint_as_float(bh[ni][0]));
                bh[ni][1] = tf32_of(f1); bl[ni][1] = tf32_of(f1 - __uint_as_float(bh[ni][1]));
            }

            #pragma unroll
            for (int mi = 0; mi < 4; ++mi)
                #pragma unroll
                for (int ni = 0; ni < 4; ++ni) {
                    MMA8(c[mi][ni], ah[mi], bh[ni]);
                    MMA8(c[mi][ni], al[mi], bh[ni]);
                    MMA8(c[mi][ni], ah[mi], bl[ni]);
                }
        }
        __syncthreads();
    }

    // epilogue
    #pragma unroll
    for (int mi = 0; mi < 4; ++mi) {
        const int r0 = blockIdx.y * 128 + wm * 64 + mi * 16 + g;
        #pragma unroll
        for (int ni = 0; ni < 4; ++ni) {
            const int col = blockIdx.x * 128 + wn * 32 + ni * 8 + tig * 2;
            float2 v0, v1;
            v0.x = c[mi][ni][0] * scale; v0.y = c[mi][ni][1] * scale;
            v1.x = c[mi][ni][2] * scale; v1.y = c[mi][ni][3] * scale;
            if (BIAS) {
                const float b0 = bias[col], b1 = bias[col + 1];
                v0.x += b0; v0.y += b1;
                v1.x += b0; v1.y += b1;
            }
            *reinterpret_cast<float2*>(C + (size_t)r0 * ldc + col) = v0;
            *reinterpret_cast<float2*>(C + (size_t)(r0 + 8) * ldc + col) = v1;
        }
    }
}

// ---------------------------------------------------------------------------
// 32x32 tiled transpose: out[j][i] = in[i][j], in is [R][C]. grid(C/32, R/32).
// ---------------------------------------------------------------------------
__global__ void __launch_bounds__(256)
transpose_kernel(const float* __restrict__ in, float* __restrict__ out, int R, int C)
{
    __shared__ float t[32][33];
    const int bx = blockIdx.x * 32, by = blockIdx.y * 32;
    const int tx = threadIdx.x, ty = threadIdx.y;
    #pragma unroll
    for (int j = 0; j < 32; j += 8)
        t[ty + j][tx] = in[(size_t)(by + ty + j) * C + bx + tx];
    __syncthreads();
    #pragma unroll
    for (int j = 0; j < 32; j += 8)
        out[(size_t)(bx + ty + j) * R + by + tx] = t[tx][ty + j];
}

// ---------------------------------------------------------------------------
// Exact per-row top-k threshold (bitonic sort) + masked softmax.
// ---------------------------------------------------------------------------
__global__ void __launch_bounds__(1024)
topk_softmax_kernel(float* __restrict__ score)
{
    __shared__ float s[N_TOK];
    __shared__ float rmax[32];
    __shared__ float rsum[32];

    float* row = score + (size_t)blockIdx.x * N_TOK;
    const int tid = threadIdx.x;

    float orig[4];
    #pragma unroll
    for (int c = 0; c < 4; ++c) {
        orig[c] = row[tid + c * 1024];
        s[tid + c * 1024] = orig[c];
    }
    __syncthreads();

    for (int kk = 2; kk <= N_TOK; kk <<= 1) {
        for (int j = kk >> 1; j > 0; j >>= 1) {
            #pragma unroll
            for (int t0 = 0; t0 < 2; ++t0) {
                const int t = tid + t0 * 1024;
                const int i = ((t & ~(j - 1)) << 1) | (t & (j - 1));
                const int l = i | j;
                const bool up = ((i & kk) == 0);
                const float a = s[i], b = s[l];
                if ((a > b) == up) { s[i] = b; s[l] = a; }
            }
            __syncthreads();
        }
    }

    const float thr = s[N_TOK - KEEP];

    float m[4];
    float lmax = 0.0f;
    #pragma unroll
    for (int c = 0; c < 4; ++c) {
        m[c] = (orig[c] > thr) ? orig[c] : 0.0f;
        lmax = fmaxf(lmax, m[c]);
    }
    #pragma unroll
    for (int o = 16; o; o >>= 1)
        lmax = fmaxf(lmax, __shfl_xor_sync(0xffffffffu, lmax, o));
    if ((tid & 31) == 0) rmax[tid >> 5] = lmax;
    __syncthreads();
    float gmax;
    {
        float v2 = rmax[tid & 31];
        #pragma unroll
        for (int o = 16; o; o >>= 1)
            v2 = fmaxf(v2, __shfl_xor_sync(0xffffffffu, v2, o));
        gmax = v2;
    }

    float e[4];
    float lsum = 0.0f;
    #pragma unroll
    for (int c = 0; c < 4; ++c) {
        e[c] = expf(m[c] - gmax);
        lsum += e[c];
    }
    #pragma unroll
    for (int o = 16; o; o >>= 1)
        lsum += __shfl_xor_sync(0xffffffffu, lsum, o);
    if ((tid & 31) == 0) rsum[tid >> 5] = lsum;
    __syncthreads();
    float gsum;
    {
        float v2 = rsum[tid & 31];
        #pragma unroll
        for (int o = 16; o; o >>= 1)
            v2 += __shfl_xor_sync(0xffffffffu, v2, o);
        gsum = v2;
    }

    const float inv = 1.0f / gsum;
    #pragma unroll
    for (int c = 0; c < 4; ++c)
        row[tid + c * 1024] = e[c] * inv;
}

// ---------------------------------------------------------------------------
// Deterministic 4-way split-K reduce (float4 granularity).
// ---------------------------------------------------------------------------
__global__ void __launch_bounds__(256)
reduce4_kernel(const float4* __restrict__ p0, const float4* __restrict__ p1,
               const float4* __restrict__ p2, const float4* __restrict__ p3,
               float4* __restrict__ out)
{
    const int i = blockIdx.x * blockDim.x + threadIdx.x;
    float4 a = p0[i], b = p1[i], c = p2[i], d = p3[i];
    float4 o;
    o.x = ((a.x + b.x) + c.x) + d.x;
    o.y = ((a.y + b.y) + c.y) + d.y;
    o.z = ((a.z + b.z) + c.z) + d.z;
    o.w = ((a.w + b.w) + c.w) + d.w;
    out[i] = o;
}

// ---------------------------------------------------------------------------
extern "C" void kernel_launch(void* const* d_in, const int* in_sizes, int n_in,
                              void* d_out, int out_size)
{
    const float* x  = (const float*)d_in[0];
    const float* Wq = (const float*)d_in[1];
    const float* bq = (const float*)d_in[2];
    const float* Wk = (const float*)d_in[3];
    const float* bk = (const float*)d_in[4];
    const float* Wv = (const float*)d_in[5];
    const float* bv = (const float*)d_in[6];
    float* out = (float*)d_out;

    float *q, *k, *v, *kT, *vT, *WT, *score, *part;
    cudaGetSymbolAddress((void**)&q,     g_q);
    cudaGetSymbolAddress((void**)&k,     g_k);
    cudaGetSymbolAddress((void**)&v,     g_v);
    cudaGetSymbolAddress((void**)&kT,    g_kT);
    cudaGetSymbolAddress((void**)&vT,    g_vT);
    cudaGetSymbolAddress((void**)&WT,    g_WT);
    cudaGetSymbolAddress((void**)&score, g_score);
    cudaGetSymbolAddress((void**)&part,  g_part);
    float* WqT = WT;
    float* WkT = WT + DDIM * DDIM;
    float* WvT = WT + 2 * DDIM * DDIM;

    cudaFuncSetAttribute(mma3t_kernel<true>,
                         cudaFuncAttributeMaxDynamicSharedMemorySize, GEMM_SMEM_BYTES);
    cudaFuncSetAttribute(mma3t_kernel<false>,
                         cudaFuncAttributeMaxDynamicSharedMemorySize, GEMM_SMEM_BYTES);

    const float inv_sqrt_d = 1.0f / sqrtf((float)DDIM);
    const dim3 tb(32, 8);

    // Weight transposes: W [in,out] -> WT [out,in]
    transpose_kernel<<<dim3(DDIM / 32, DDIM / 32), tb>>>(Wq, WqT, DDIM, DDIM);
    transpose_kernel<<<dim3(DDIM / 32, DDIM / 32), tb>>>(Wk, WkT, DDIM, DDIM);
    transpose_kernel<<<dim3(DDIM / 32, DDIM / 32), tb>>>(Wv, WvT, DDIM, DDIM);

    // QKV: M=4096, N=512, K=512
    {
        dim3 grid(DDIM / 128, N_TOK / 128);
        mma3t_kernel<true><<<grid, 256, GEMM_SMEM_BYTES>>>(x, DDIM, WqT, DDIM, q, DDIM, DDIM, bq, 1.0f);
        mma3t_kernel<true><<<grid, 256, GEMM_SMEM_BYTES>>>(x, DDIM, WkT, DDIM, k, DDIM, DDIM, bk, 1.0f);
        mma3t_kernel<true><<<grid, 256, GEMM_SMEM_BYTES>>>(x, DDIM, WvT, DDIM, v, DDIM, DDIM, bv, 1.0f);
    }

    // kT[n][dd] = k_mat[dd][n] where k_mat = k viewed as [512][4096]
    transpose_kernel<<<dim3(N_TOK / 32, DDIM / 32), tb>>>(k, kT, DDIM, N_TOK);
    // vT[d][t] = v[t][d]
    transpose_kernel<<<dim3(DDIM / 32, N_TOK / 32), tb>>>(v, vT, N_TOK, DDIM);

    // Score: M=N=4096, K=512, scaled
    {
        dim3 grid(N_TOK / 128, N_TOK / 128);
        mma3t_kernel<false><<<grid, 256, GEMM_SMEM_BYTES>>>(q, DDIM, kT, DDIM, score, N_TOK,
                                                            DDIM, nullptr, inv_sqrt_d);
    }

    // Exact top-k threshold + masked softmax (in-place)
    topk_softmax_kernel<<<N_TOK, 1024>>>(score);

    // Context: M=4096, N=512, K=4096 via split-K=4
    {
        dim3 grid(DDIM / 128, N_TOK / 128);
        for (int s = 0; s < 4; ++s) {
            mma3t_kernel<false><<<grid, 256, GEMM_SMEM_BYTES>>>(
                score + s * (N_TOK / 4), N_TOK,
                vT    + s * (N_TOK / 4), N_TOK,
                part + (size_t)s * N_TOK * DDIM, DDIM,
                N_TOK / 4, nullptr, 1.0f);
        }
        reduce4_kernel<<<(N_TOK * DDIM / 4) / 256, 256>>>(
            (const float4*)(part + 0 * (size_t)N_TOK * DDIM),
            (const float4*)(part + 1 * (size_t)N_TOK * DDIM),
            (const float4*)(part + 2 * (size_t)N_TOK * DDIM),
            (const float4*)(part + 3 * (size_t)N_TOK * DDIM),
            (float4*)out);
    }
}

// round 4
// speedup vs baseline: 1.7806x; 1.4675x over previous
#include <cuda_runtime.h>
#include <cstdint>
#include <math.h>

#define N_TOK 4096
#define DDIM  512
#define KEEP  2048

// ---------------- device scratch (allocation-free) ----------------
__device__ float g_q [N_TOK * DDIM];
__device__ float g_k [N_TOK * DDIM];
__device__ float g_v [N_TOK * DDIM];
__device__ float g_kT[N_TOK * DDIM];
__device__ float g_vT[N_TOK * DDIM];
__device__ float g_WT[3][DDIM * DDIM];
__device__ float g_score[(size_t)N_TOK * N_TOK];
__device__ float g_part[4][N_TOK * DDIM];

// ---------------- helpers ----------------
__device__ __forceinline__ uint32_t smem_u32(const void* p) {
    uint32_t a;
    asm("{ .reg .u64 t; cvta.to.shared.u64 t, %1; cvt.u32.u64 %0, t; }"
        : "=r"(a) : "l"(p));
    return a;
}
__device__ __forceinline__ uint32_t tf32_of(float f) {
    uint32_t u;
    asm("cvt.rna.tf32.f32 %0, %1;" : "=r"(u) : "f"(f));
    return u;
}

#define CP16(dst, src) \
    asm volatile("cp.async.cg.shared.global [%0], [%1], 16;" :: "r"(dst), "l"(src) : "memory")
#define CP_COMMIT() asm volatile("cp.async.commit_group;" ::: "memory")
#define CP_WAIT1()  asm volatile("cp.async.wait_group 1;" ::: "memory")
#define CP_WAIT0()  asm volatile("cp.async.wait_group 0;" ::: "memory")

// m16n8k8 tf32 MMA, D += A*B  (row.col)
#define MMA8(cc, a, b)                                                          \
    asm volatile("mma.sync.aligned.m16n8k8.row.col.f32.tf32.tf32.f32 "          \
        "{%0,%1,%2,%3}, {%4,%5,%6,%7}, {%8,%9}, {%0,%1,%2,%3};"                 \
        : "+f"((cc)[0]), "+f"((cc)[1]), "+f"((cc)[2]), "+f"((cc)[3])            \
        : "r"((a)[0]), "r"((a)[1]), "r"((a)[2]), "r"((a)[3]),                   \
          "r"((b)[0]), "r"((b)[1]))

// ---------------------------------------------------------------------------
// 3xTF32 mma.sync GEMM: C[M,N] = scale*(A @ B^T) (+bias)
// Block 128x128, BK=32, 256 threads, 8 warps 2(m)x4(n), warp tile 64x32.
// Split terms issued as 3 groups of 16 INDEPENDENT MMAs (accumulator reuse
// distance 16) to break the RAW chains seen in R3 (tensor pipe 42.5%).
// ---------------------------------------------------------------------------
#define TILE_F   (128 * 36)
#define STAGE_B  (2 * TILE_F * 4)
#define GEMM_SMEM_BYTES (2 * STAGE_B)     // 73728

template<bool BIAS>
__global__ void __launch_bounds__(256, 1)
mma3t_kernel(const float* __restrict__ A, int lda,
             const float* __restrict__ B, int ldb,
             float* __restrict__ C, int ldc,
             int K, const float* __restrict__ bias, float scale)
{
    extern __shared__ char sm[];
    const uint32_t smb = smem_u32(sm);

    const int tid  = threadIdx.x;
    const int w    = tid >> 5;
    const int lane = tid & 31;
    const int wm   = w & 1;
    const int wn   = w >> 1;
    const int g    = lane >> 2;
    const int tig  = lane & 3;

    const int lrow = tid >> 1;
    const int lcol = (tid & 1) * 16;
    const float* Ap = A + (size_t)(blockIdx.y * 128 + lrow) * lda + lcol;
    const float* Bp = B + (size_t)(blockIdx.x * 128 + lrow) * ldb + lcol;
    const uint32_t sAo = (uint32_t)(lrow * 36 + lcol) * 4;
    const uint32_t sBo = sAo + TILE_F * 4;

    float c[4][4][4] = {};

    const int nT = K >> 5;

    {
        const uint32_t st = smb;
        #pragma unroll
        for (int j = 0; j < 4; ++j) {
            CP16(st + sAo + j * 16, Ap + j * 4);
            CP16(st + sBo + j * 16, Bp + j * 4);
        }
        CP_COMMIT();
    }

    for (int kt = 0; kt < nT; ++kt) {
        if (kt + 1 < nT) {
            const uint32_t st = smb + ((kt + 1) & 1) * STAGE_B;
            const float* a1 = Ap + (kt + 1) * 32;
            const float* b1 = Bp + (kt + 1) * 32;
            #pragma unroll
            for (int j = 0; j < 4; ++j) {
                CP16(st + sAo + j * 16, a1 + j * 4);
                CP16(st + sBo + j * 16, b1 + j * 4);
            }
            CP_COMMIT();
            CP_WAIT1();
        } else {
            CP_WAIT0();
        }
        __syncthreads();

        const float* As = (const float*)(sm + (kt & 1) * STAGE_B);
        const float* Bs = As + TILE_F;

        #pragma unroll
        for (int ks = 0; ks < 4; ++ks) {
            const int kb = ks * 8;

            uint32_t ah[4][4], al[4][4];
            #pragma unroll
            for (int mi = 0; mi < 4; ++mi) {
                const int r0 = wm * 64 + mi * 16 + g;
                const float f0 = As[r0 * 36 + kb + tig];
                const float f1 = As[(r0 + 8) * 36 + kb + tig];
                const float f2 = As[r0 * 36 + kb + tig + 4];
                const float f3 = As[(r0 + 8) * 36 + kb + tig + 4];
                ah[mi][0] = tf32_of(f0); al[mi][0] = tf32_of(f0 - __uint_as_float(ah[mi][0]));
                ah[mi][1] = tf32_of(f1); al[mi][1] = tf32_of(f1 - __uint_as_float(ah[mi][1]));
                ah[mi][2] = tf32_of(f2); al[mi][2] = tf32_of(f2 - __uint_as_float(ah[mi][2]));
                ah[mi][3] = tf32_of(f3); al[mi][3] = tf32_of(f3 - __uint_as_float(ah[mi][3]));
            }
            uint32_t bh[4][2], bl[4][2];
            #pragma unroll
            for (int ni = 0; ni < 4; ++ni) {
                const int rb = wn * 32 + ni * 8 + g;
                const float f0 = Bs[rb * 36 + kb + tig];
                const float f1 = Bs[rb * 36 + kb + tig + 4];
                bh[ni][0] = tf32_of(f0); bl[ni][0] = tf32_of(f0 - __uint_as_float(bh[ni][0]));
                bh[ni][1] = tf32_of(f1); bl[ni][1] = tf32_of(f1 - __uint_as_float(bh[ni][1]));
            }

            // term hi*hi : 16 independent MMAs
            #pragma unroll
            for (int mi = 0; mi < 4; ++mi)
                #pragma unroll
                for (int ni = 0; ni < 4; ++ni)
                    MMA8(c[mi][ni], ah[mi], bh[ni]);
            // term lo*hi
            #pragma unroll
            for (int mi = 0; mi < 4; ++mi)
                #pragma unroll
                for (int ni = 0; ni < 4; ++ni)
                    MMA8(c[mi][ni], al[mi], bh[ni]);
            // term hi*lo
            #pragma unroll
            for (int mi = 0; mi < 4; ++mi)
                #pragma unroll
                for (int ni = 0; ni < 4; ++ni)
                    MMA8(c[mi][ni], ah[mi], bl[ni]);
        }
        __syncthreads();
    }

    #pragma unroll
    for (int mi = 0; mi < 4; ++mi) {
        const int r0 = blockIdx.y * 128 + wm * 64 + mi * 16 + g;
        #pragma unroll
        for (int ni = 0; ni < 4; ++ni) {
            const int col = blockIdx.x * 128 + wn * 32 + ni * 8 + tig * 2;
            float2 v0, v1;
            v0.x = c[mi][ni][0] * scale; v0.y = c[mi][ni][1] * scale;
            v1.x = c[mi][ni][2] * scale; v1.y = c[mi][ni][3] * scale;
            if (BIAS) {
                const float b0 = bias[col], b1 = bias[col + 1];
                v0.x += b0; v0.y += b1;
                v1.x += b0; v1.y += b1;
            }
            *reinterpret_cast<float2*>(C + (size_t)r0 * ldc + col) = v0;
            *reinterpret_cast<float2*>(C + (size_t)(r0 + 8) * ldc + col) = v1;
        }
    }
}

// ---------------------------------------------------------------------------
// 32x32 tiled transpose
// ---------------------------------------------------------------------------
__global__ void __launch_bounds__(256)
transpose_kernel(const float* __restrict__ in, float* __restrict__ out, int R, int C)
{
    __shared__ float t[32][33];
    const int bx = blockIdx.x * 32, by = blockIdx.y * 32;
    const int tx = threadIdx.x, ty = threadIdx.y;
    #pragma unroll
    for (int j = 0; j < 32; j += 8)
        t[ty + j][tx] = in[(size_t)(by + ty + j) * C + bx + tx];
    __syncthreads();
    #pragma unroll
    for (int j = 0; j < 32; j += 8)
        out[(size_t)(bx + ty + j) * R + by + tx] = t[tx][ty + j];
}

// ---------------------------------------------------------------------------
// Exact per-row top-k threshold via 4-pass radix select on monotonically
// transformed float bits, fused with masked softmax. One block (512 thr)/row.
// Transform: u = bits(f) ^ (((int)bits>>31) | 0x80000000) — order-preserving,
// so selection AND the strict-> compare are bitwise exact vs a full sort.
// ---------------------------------------------------------------------------
__global__ void __launch_bounds__(512)
topk_softmax_kernel(float* __restrict__ score)
{
    __shared__ uint32_t s[N_TOK];
    __shared__ uint32_t hist[256];
    __shared__ uint32_t sh_sel[2];     // {prefix, rank}
    __shared__ float red[16];

    const int tid = threadIdx.x;
    float* row = score + (size_t)blockIdx.x * N_TOK;

    float orig[8];
    uint32_t su[8];
    #pragma unroll
    for (int cidx = 0; cidx < 8; ++cidx) {
        const float f = row[tid + cidx * 512];
        orig[cidx] = f;
        uint32_t u = __float_as_uint(f);
        u ^= (uint32_t)(((int32_t)u) >> 31) | 0x80000000u;
        su[cidx] = u;
        s[tid + cidx * 512] = u;
    }

    uint32_t prefix = 0, rank = KEEP;
    #pragma unroll
    for (int pass = 0; pass < 4; ++pass) {
        const int shift   = 24 - pass * 8;
        const int hishift = (pass == 0) ? 0 : (shift + 8);
        if (tid < 256) hist[tid] = 0;
        __syncthreads();
        #pragma unroll
        for (int cidx = 0; cidx < 8; ++cidx) {
            const uint32_t u = s[tid + cidx * 512];
            const bool match = (pass == 0) || (((u ^ prefix) >> hishift) == 0);
            if (match) atomicAdd(&hist[(u >> shift) & 0xFFu], 1u);
        }
        __syncthreads();
        if (tid < 32) {
            // warp-parallel descending cumulative over 256 bins (8 bins/lane)
            uint32_t h[8], sum = 0;
            #pragma unroll
            for (int i = 0; i < 8; ++i) {
                h[i] = hist[255 - (tid * 8 + i)];
                sum += h[i];
            }
            uint32_t inc = sum;
            #pragma unroll
            for (int o = 1; o < 32; o <<= 1) {
                const uint32_t t = __shfl_up_sync(0xffffffffu, inc, o);
                if (tid >= o) inc += t;
            }
            const uint32_t exc = inc - sum;
            if (exc < rank && rank <= inc) {
                uint32_t cum = exc;
                #pragma unroll
                for (int i = 0; i < 8; ++i) {
                    cum += h[i];
                    if (cum >= rank) {
                        sh_sel[0] = prefix | ((uint32_t)(255 - (tid * 8 + i)) << shift);
                        sh_sel[1] = rank - (cum - h[i]);
                        break;
                    }
                }
            }
        }
        __syncthreads();
        prefix = sh_sel[0];
        rank   = sh_sel[1];
        __syncthreads();
    }
    const uint32_t thr_u = prefix;   // exact KEEP-th largest (transformed)

    // masked softmax (strict > in transformed space == strict > on floats)
    float m[8];
    float lmax = 0.0f;
    #pragma unroll
    for (int cidx = 0; cidx < 8; ++cidx) {
        m[cidx] = (su[cidx] > thr_u) ? orig[cidx] : 0.0f;
        lmax = fmaxf(lmax, m[cidx]);
    }
    #pragma unroll
    for (int o = 16; o; o >>= 1)
        lmax = fmaxf(lmax, __shfl_xor_sync(0xffffffffu, lmax, o));
    if ((tid & 31) == 0) red[tid >> 5] = lmax;
    __syncthreads();
    float gmax;
    {
        float v2 = red[tid & 15];
        #pragma unroll
        for (int o = 8; o; o >>= 1)
            v2 = fmaxf(v2, __shfl_xor_sync(0xffffffffu, v2, o));
        gmax = v2;
    }
    __syncthreads();

    float e[8];
    float lsum = 0.0f;
    #pragma unroll
    for (int cidx = 0; cidx < 8; ++cidx) {
        e[cidx] = expf(m[cidx] - gmax);
        lsum += e[cidx];
    }
    #pragma unroll
    for (int o = 16; o; o >>= 1)
        lsum += __shfl_xor_sync(0xffffffffu, lsum, o);
    if ((tid & 31) == 0) red[tid >> 5] = lsum;
    __syncthreads();
    float gsum;
    {
        float v2 = red[tid & 15];
        #pragma unroll
        for (int o = 8; o; o >>= 1)
            v2 += __shfl_xor_sync(0xffffffffu, v2, o);
        gsum = v2;
    }

    const float inv = 1.0f / gsum;
    #pragma unroll
    for (int cidx = 0; cidx < 8; ++cidx)
        row[tid + cidx * 512] = e[cidx] * inv;
}

// ---------------------------------------------------------------------------
// Deterministic 4-way split-K reduce
// ---------------------------------------------------------------------------
__global__ void __launch_bounds__(256)
reduce4_kernel(const float4* __restrict__ p0, const float4* __restrict__ p1,
               const float4* __restrict__ p2, const float4* __restrict__ p3,
               float4* __restrict__ out)
{
    const int i = blockIdx.x * blockDim.x + threadIdx.x;
    float4 a = p0[i], b = p1[i], c = p2[i], d = p3[i];
    float4 o;
    o.x = ((a.x + b.x) + c.x) + d.x;
    o.y = ((a.y + b.y) + c.y) + d.y;
    o.z = ((a.z + b.z) + c.z) + d.z;
    o.w = ((a.w + b.w) + c.w) + d.w;
    out[i] = o;
}

// ---------------------------------------------------------------------------
extern "C" void kernel_launch(void* const* d_in, const int* in_sizes, int n_in,
                              void* d_out, int out_size)
{
    const float* x  = (const float*)d_in[0];
    const float* Wq = (const float*)d_in[1];
    const float* bq = (const float*)d_in[2];
    const float* Wk = (const float*)d_in[3];
    const float* bk = (const float*)d_in[4];
    const float* Wv = (const float*)d_in[5];
    const float* bv = (const float*)d_in[6];
    float* out = (float*)d_out;

    float *q, *k, *v, *kT, *vT, *WT, *score, *part;
    cudaGetSymbolAddress((void**)&q,     g_q);
    cudaGetSymbolAddress((void**)&k,     g_k);
    cudaGetSymbolAddress((void**)&v,     g_v);
    cudaGetSymbolAddress((void**)&kT,    g_kT);
    cudaGetSymbolAddress((void**)&vT,    g_vT);
    cudaGetSymbolAddress((void**)&WT,    g_WT);
    cudaGetSymbolAddress((void**)&score, g_score);
    cudaGetSymbolAddress((void**)&part,  g_part);
    float* WqT = WT;
    float* WkT = WT + DDIM * DDIM;
    float* WvT = WT + 2 * DDIM * DDIM;

    cudaFuncSetAttribute(mma3t_kernel<true>,
                         cudaFuncAttributeMaxDynamicSharedMemorySize, GEMM_SMEM_BYTES);
    cudaFuncSetAttribute(mma3t_kernel<false>,
                         cudaFuncAttributeMaxDynamicSharedMemorySize, GEMM_SMEM_BYTES);

    const float inv_sqrt_d = 1.0f / sqrtf((float)DDIM);
    const dim3 tb(32, 8);

    transpose_kernel<<<dim3(DDIM / 32, DDIM / 32), tb>>>(Wq, WqT, DDIM, DDIM);
    transpose_kernel<<<dim3(DDIM / 32, DDIM / 32), tb>>>(Wk, WkT, DDIM, DDIM);
    transpose_kernel<<<dim3(DDIM / 32, DDIM / 32), tb>>>(Wv, WvT, DDIM, DDIM);

    // QKV: M=4096, N=512, K=512
    {
        dim3 grid(DDIM / 128, N_TOK / 128);
        mma3t_kernel<true><<<grid, 256, GEMM_SMEM_BYTES>>>(x, DDIM, WqT, DDIM, q, DDIM, DDIM, bq, 1.0f);
        mma3t_kernel<true><<<grid, 256, GEMM_SMEM_BYTES>>>(x, DDIM, WkT, DDIM, k, DDIM, DDIM, bk, 1.0f);
        mma3t_kernel<true><<<grid, 256, GEMM_SMEM_BYTES>>>(x, DDIM, WvT, DDIM, v, DDIM, DDIM, bv, 1.0f);
    }

    // kT[n][dd] = (k viewed as [512][4096])^T ; vT = v^T
    transpose_kernel<<<dim3(N_TOK / 32, DDIM / 32), tb>>>(k, kT, DDIM, N_TOK);
    transpose_kernel<<<dim3(DDIM / 32, N_TOK / 32), tb>>>(v, vT, N_TOK, DDIM);

    // Score: M=N=4096, K=512
    {
        dim3 grid(N_TOK / 128, N_TOK / 128);
        mma3t_kernel<false><<<grid, 256, GEMM_SMEM_BYTES>>>(q, DDIM, kT, DDIM, score, N_TOK,
                                                            DDIM, nullptr, inv_sqrt_d);
    }

    // Exact top-k threshold + masked softmax (in-place, radix select)
    topk_softmax_kernel<<<N_TOK, 512>>>(score);

    // Context: M=4096, N=512, K=4096 via split-K=4
    {
        dim3 grid(DDIM / 128, N_TOK / 128);
        for (int sidx = 0; sidx < 4; ++sidx) {
            mma3t_kernel<false><<<grid, 256, GEMM_SMEM_BYTES>>>(
                score + sidx * (N_TOK / 4), N_TOK,
                vT    + sidx * (N_TOK / 4), N_TOK,
                part + (size_t)sidx * N_TOK * DDIM, DDIM,
                N_TOK / 4, nullptr, 1.0f);
        }
        reduce4_kernel<<<(N_TOK * DDIM / 4) / 256, 256>>>(
            (const float4*)(part + 0 * (size_t)N_TOK * DDIM),
            (const float4*)(part + 1 * (size_t)N_TOK * DDIM),
            (const float4*)(part + 2 * (size_t)N_TOK * DDIM),
            (const float4*)(part + 3 * (size_t)N_TOK * DDIM),
            (float4*)out);
    }
}

// round 5
// speedup vs baseline: 1.8660x; 1.0480x over previous
#include <cuda_runtime.h>
#include <cstdint>
#include <math.h>

#define N_TOK 4096
#define DDIM  512
#define KEEP  2048

// ---------------- device scratch (allocation-free) ----------------
__device__ float g_q [N_TOK * DDIM];
__device__ float g_k [N_TOK * DDIM];
__device__ float g_v [N_TOK * DDIM];
__device__ float g_kT[N_TOK * DDIM];
__device__ float g_vT[N_TOK * DDIM];
__device__ float g_WT[3][DDIM * DDIM];
__device__ float g_score[(size_t)N_TOK * N_TOK];
__device__ float g_part[4][N_TOK * DDIM];

// ---------------- helpers ----------------
__device__ __forceinline__ uint32_t smem_u32(const void* p) {
    uint32_t a;
    asm("{ .reg .u64 t; cvta.to.shared.u64 t, %1; cvt.u32.u64 %0, t; }"
        : "=r"(a) : "l"(p));
    return a;
}
__device__ __forceinline__ uint32_t tf32_of(float f) {
    uint32_t u;
    asm("cvt.rna.tf32.f32 %0, %1;" : "=r"(u) : "f"(f));
    return u;
}

#define CP16(dst, src) \
    asm volatile("cp.async.cg.shared.global [%0], [%1], 16;" :: "r"(dst), "l"(src) : "memory")
#define CP_COMMIT() asm volatile("cp.async.commit_group;" ::: "memory")
#define CP_WAIT1()  asm volatile("cp.async.wait_group 1;" ::: "memory")
#define CP_WAIT0()  asm volatile("cp.async.wait_group 0;" ::: "memory")

// m16n8k8 tf32 MMA, D += A*B  (row.col)
#define MMA8(cc, a, b)                                                          \
    asm volatile("mma.sync.aligned.m16n8k8.row.col.f32.tf32.tf32.f32 "          \
        "{%0,%1,%2,%3}, {%4,%5,%6,%7}, {%8,%9}, {%0,%1,%2,%3};"                 \
        : "+f"((cc)[0]), "+f"((cc)[1]), "+f"((cc)[2]), "+f"((cc)[3])            \
        : "r"((a)[0]), "r"((a)[1]), "r"((a)[2]), "r"((a)[3]),                   \
          "r"((b)[0]), "r"((b)[1]))

// ---------------------------------------------------------------------------
// 3xTF32 mma.sync GEMM: C[M,N] = scale*(A @ B^T) (+bias)
// Block 128x128, BK=32, **512 threads / 16 warps** in 4(m)x4(n), warp tile
// 32x32. Vs R4 (256 thr): per-warp register state halved -> 4 warps/SMSP
// instead of 2, attacking the issue=34.5% latency ceiling.
// Smem: double-buffered raw fp32 tiles As[128][36] + Bs[128][36].
// ---------------------------------------------------------------------------
#define TILE_F   (128 * 36)
#define STAGE_B  (2 * TILE_F * 4)
#define GEMM_SMEM_BYTES (2 * STAGE_B)     // 73728

template<bool BIAS>
__global__ void __launch_bounds__(512, 1)
mma3t_kernel(const float* __restrict__ A, int lda,
             const float* __restrict__ B, int ldb,
             float* __restrict__ C, int ldc,
             int K, const float* __restrict__ bias, float scale)
{
    extern __shared__ char sm[];
    const uint32_t smb = smem_u32(sm);

    const int tid  = threadIdx.x;
    const int w    = tid >> 5;
    const int lane = tid & 31;
    const int wm   = w & 3;           // 0..3 (rows)
    const int wn   = w >> 2;          // 0..3 (cols)
    const int g    = lane >> 2;       // 0..7
    const int tig  = lane & 3;        // 0..3

    // global loader: thread t -> row t>>2, 8-float quarter (t&3)
    const int lrow = tid >> 2;
    const int lcol = (tid & 3) * 8;
    const float* Ap = A + (size_t)(blockIdx.y * 128 + lrow) * lda + lcol;
    const float* Bp = B + (size_t)(blockIdx.x * 128 + lrow) * ldb + lcol;
    const uint32_t sAo = (uint32_t)(lrow * 36 + lcol) * 4;
    const uint32_t sBo = sAo + TILE_F * 4;

    float c[2][4][4] = {};

    const int nT = K >> 5;

    {
        const uint32_t st = smb;
        #pragma unroll
        for (int j = 0; j < 2; ++j) {
            CP16(st + sAo + j * 16, Ap + j * 4);
            CP16(st + sBo + j * 16, Bp + j * 4);
        }
        CP_COMMIT();
    }

    for (int kt = 0; kt < nT; ++kt) {
        if (kt + 1 < nT) {
            const uint32_t st = smb + ((kt + 1) & 1) * STAGE_B;
            const float* a1 = Ap + (kt + 1) * 32;
            const float* b1 = Bp + (kt + 1) * 32;
            #pragma unroll
            for (int j = 0; j < 2; ++j) {
                CP16(st + sAo + j * 16, a1 + j * 4);
                CP16(st + sBo + j * 16, b1 + j * 4);
            }
            CP_COMMIT();
            CP_WAIT1();
        } else {
            CP_WAIT0();
        }
        __syncthreads();

        const float* As = (const float*)(sm + (kt & 1) * STAGE_B);
        const float* Bs = As + TILE_F;

        #pragma unroll
        for (int ks = 0; ks < 4; ++ks) {
            const int kb = ks * 8;

            uint32_t ah[2][4], al[2][4];
            #pragma unroll
            for (int mi = 0; mi < 2; ++mi) {
                const int r0 = wm * 32 + mi * 16 + g;
                const float f0 = As[r0 * 36 + kb + tig];
                const float f1 = As[(r0 + 8) * 36 + kb + tig];
                const float f2 = As[r0 * 36 + kb + tig + 4];
                const float f3 = As[(r0 + 8) * 36 + kb + tig + 4];
                ah[mi][0] = tf32_of(f0); al[mi][0] = tf32_of(f0 - __uint_as_float(ah[mi][0]));
                ah[mi][1] = tf32_of(f1); al[mi][1] = tf32_of(f1 - __uint_as_float(ah[mi][1]));
                ah[mi][2] = tf32_of(f2); al[mi][2] = tf32_of(f2 - __uint_as_float(ah[mi][2]));
                ah[mi][3] = tf32_of(f3); al[mi][3] = tf32_of(f3 - __uint_as_float(ah[mi][3]));
            }
            uint32_t bh[4][2], bl[4][2];
            #pragma unroll
            for (int ni = 0; ni < 4; ++ni) {
                const int rb = wn * 32 + ni * 8 + g;
                const float f0 = Bs[rb * 36 + kb + tig];
                const float f1 = Bs[rb * 36 + kb + tig + 4];
                bh[ni][0] = tf32_of(f0); bl[ni][0] = tf32_of(f0 - __uint_as_float(bh[ni][0]));
                bh[ni][1] = tf32_of(f1); bl[ni][1] = tf32_of(f1 - __uint_as_float(bh[ni][1]));
            }

            #pragma unroll
            for (int mi = 0; mi < 2; ++mi)
                #pragma unroll
                for (int ni = 0; ni < 4; ++ni)
                    MMA8(c[mi][ni], ah[mi], bh[ni]);
            #pragma unroll
            for (int mi = 0; mi < 2; ++mi)
                #pragma unroll
                for (int ni = 0; ni < 4; ++ni)
                    MMA8(c[mi][ni], al[mi], bh[ni]);
            #pragma unroll
            for (int mi = 0; mi < 2; ++mi)
                #pragma unroll
                for (int ni = 0; ni < 4; ++ni)
                    MMA8(c[mi][ni], ah[mi], bl[ni]);
        }
        __syncthreads();
    }

    #pragma unroll
    for (int mi = 0; mi < 2; ++mi) {
        const int r0 = blockIdx.y * 128 + wm * 32 + mi * 16 + g;
        #pragma unroll
        for (int ni = 0; ni < 4; ++ni) {
            const int col = blockIdx.x * 128 + wn * 32 + ni * 8 + tig * 2;
            float2 v0, v1;
            v0.x = c[mi][ni][0] * scale; v0.y = c[mi][ni][1] * scale;
            v1.x = c[mi][ni][2] * scale; v1.y = c[mi][ni][3] * scale;
            if (BIAS) {
                const float b0 = bias[col], b1 = bias[col + 1];
                v0.x += b0; v0.y += b1;
                v1.x += b0; v1.y += b1;
            }
            *reinterpret_cast<float2*>(C + (size_t)r0 * ldc + col) = v0;
            *reinterpret_cast<float2*>(C + (size_t)(r0 + 8) * ldc + col) = v1;
        }
    }
}

// ---------------------------------------------------------------------------
// 32x32 tiled transpose
// ---------------------------------------------------------------------------
__global__ void __launch_bounds__(256)
transpose_kernel(const float* __restrict__ in, float* __restrict__ out, int R, int C)
{
    __shared__ float t[32][33];
    const int bx = blockIdx.x * 32, by = blockIdx.y * 32;
    const int tx = threadIdx.x, ty = threadIdx.y;
    #pragma unroll
    for (int j = 0; j < 32; j += 8)
        t[ty + j][tx] = in[(size_t)(by + ty + j) * C + bx + tx];
    __syncthreads();
    #pragma unroll
    for (int j = 0; j < 32; j += 8)
        out[(size_t)(bx + ty + j) * R + by + tx] = t[tx][ty + j];
}

// ---------------------------------------------------------------------------
// Exact per-row top-k threshold via 4-pass radix select on monotonically
// transformed float bits, fused with masked softmax. One block (512 thr)/row.
// ---------------------------------------------------------------------------
__global__ void __launch_bounds__(512)
topk_softmax_kernel(float* __restrict__ score)
{
    __shared__ uint32_t s[N_TOK];
    __shared__ uint32_t hist[256];
    __shared__ uint32_t sh_sel[2];     // {prefix, rank}
    __shared__ float red[16];

    const int tid = threadIdx.x;
    float* row = score + (size_t)blockIdx.x * N_TOK;

    float orig[8];
    uint32_t su[8];
    #pragma unroll
    for (int cidx = 0; cidx < 8; ++cidx) {
        const float f = row[tid + cidx * 512];
        orig[cidx] = f;
        uint32_t u = __float_as_uint(f);
        u ^= (uint32_t)(((int32_t)u) >> 31) | 0x80000000u;
        su[cidx] = u;
        s[tid + cidx * 512] = u;
    }

    uint32_t prefix = 0, rank = KEEP;
    #pragma unroll
    for (int pass = 0; pass < 4; ++pass) {
        const int shift   = 24 - pass * 8;
        const int hishift = (pass == 0) ? 0 : (shift + 8);
        if (tid < 256) hist[tid] = 0;
        __syncthreads();
        #pragma unroll
        for (int cidx = 0; cidx < 8; ++cidx) {
            const uint32_t u = s[tid + cidx * 512];
            const bool match = (pass == 0) || (((u ^ prefix) >> hishift) == 0);
            if (match) atomicAdd(&hist[(u >> shift) & 0xFFu], 1u);
        }
        __syncthreads();
        if (tid < 32) {
            uint32_t h[8], sum = 0;
            #pragma unroll
            for (int i = 0; i < 8; ++i) {
                h[i] = hist[255 - (tid * 8 + i)];
                sum += h[i];
            }
            uint32_t inc = sum;
            #pragma unroll
            for (int o = 1; o < 32; o <<= 1) {
                const uint32_t t = __shfl_up_sync(0xffffffffu, inc, o);
                if (tid >= o) inc += t;
            }
            const uint32_t exc = inc - sum;
            if (exc < rank && rank <= inc) {
                uint32_t cum = exc;
                #pragma unroll
                for (int i = 0; i < 8; ++i) {
                    cum += h[i];
                    if (cum >= rank) {
                        sh_sel[0] = prefix | ((uint32_t)(255 - (tid * 8 + i)) << shift);
                        sh_sel[1] = rank - (cum - h[i]);
                        break;
                    }
                }
            }
        }
        __syncthreads();
        prefix = sh_sel[0];
        rank   = sh_sel[1];
        __syncthreads();
    }
    const uint32_t thr_u = prefix;

    float m[8];
    float lmax = 0.0f;
    #pragma unroll
    for (int cidx = 0; cidx < 8; ++cidx) {
        m[cidx] = (su[cidx] > thr_u) ? orig[cidx] : 0.0f;
        lmax = fmaxf(lmax, m[cidx]);
    }
    #pragma unroll
    for (int o = 16; o; o >>= 1)
        lmax = fmaxf(lmax, __shfl_xor_sync(0xffffffffu, lmax, o));
    if ((tid & 31) == 0) red[tid >> 5] = lmax;
    __syncthreads();
    float gmax;
    {
        float v2 = red[tid & 15];
        #pragma unroll
        for (int o = 8; o; o >>= 1)
            v2 = fmaxf(v2, __shfl_xor_sync(0xffffffffu, v2, o));
        gmax = v2;
    }
    __syncthreads();

    float e[8];
    float lsum = 0.0f;
    #pragma unroll
    for (int cidx = 0; cidx < 8; ++cidx) {
        e[cidx] = expf(m[cidx] - gmax);
        lsum += e[cidx];
    }
    #pragma unroll
    for (int o = 16; o; o >>= 1)
        lsum += __shfl_xor_sync(0xffffffffu, lsum, o);
    if ((tid & 31) == 0) red[tid >> 5] = lsum;
    __syncthreads();
    float gsum;
    {
        float v2 = red[tid & 15];
        #pragma unroll
        for (int o = 8; o; o >>= 1)
            v2 += __shfl_xor_sync(0xffffffffu, v2, o);
        gsum = v2;
    }

    const float inv = 1.0f / gsum;
    #pragma unroll
    for (int cidx = 0; cidx < 8; ++cidx)
        row[tid + cidx * 512] = e[cidx] * inv;
}

// ---------------------------------------------------------------------------
// Deterministic 4-way split-K reduce
// ---------------------------------------------------------------------------
__global__ void __launch_bounds__(256)
reduce4_kernel(const float4* __restrict__ p0, const float4* __restrict__ p1,
               const float4* __restrict__ p2, const float4* __restrict__ p3,
               float4* __restrict__ out)
{
    const int i = blockIdx.x * blockDim.x + threadIdx.x;
    float4 a = p0[i], b = p1[i], c = p2[i], d = p3[i];
    float4 o;
    o.x = ((a.x + b.x) + c.x) + d.x;
    o.y = ((a.y + b.y) + c.y) + d.y;
    o.z = ((a.z + b.z) + c.z) + d.z;
    o.w = ((a.w + b.w) + c.w) + d.w;
    out[i] = o;
}

// ---------------------------------------------------------------------------
extern "C" void kernel_launch(void* const* d_in, const int* in_sizes, int n_in,
                              void* d_out, int out_size)
{
    const float* x  = (const float*)d_in[0];
    const float* Wq = (const float*)d_in[1];
    const float* bq = (const float*)d_in[2];
    const float* Wk = (const float*)d_in[3];
    const float* bk = (const float*)d_in[4];
    const float* Wv = (const float*)d_in[5];
    const float* bv = (const float*)d_in[6];
    float* out = (float*)d_out;

    float *q, *k, *v, *kT, *vT, *WT, *score, *part;
    cudaGetSymbolAddress((void**)&q,     g_q);
    cudaGetSymbolAddress((void**)&k,     g_k);
    cudaGetSymbolAddress((void**)&v,     g_v);
    cudaGetSymbolAddress((void**)&kT,    g_kT);
    cudaGetSymbolAddress((void**)&vT,    g_vT);
    cudaGetSymbolAddress((void**)&WT,    g_WT);
    cudaGetSymbolAddress((void**)&score, g_score);
    cudaGetSymbolAddress((void**)&part,  g_part);
    float* WqT = WT;
    float* WkT = WT + DDIM * DDIM;
    float* WvT = WT + 2 * DDIM * DDIM;

    cudaFuncSetAttribute(mma3t_kernel<true>,
                         cudaFuncAttributeMaxDynamicSharedMemorySize, GEMM_SMEM_BYTES);
    cudaFuncSetAttribute(mma3t_kernel<false>,
                         cudaFuncAttributeMaxDynamicSharedMemorySize, GEMM_SMEM_BYTES);

    const float inv_sqrt_d = 1.0f / sqrtf((float)DDIM);
    const dim3 tb(32, 8);

    transpose_kernel<<<dim3(DDIM / 32, DDIM / 32), tb>>>(Wq, WqT, DDIM, DDIM);
    transpose_kernel<<<dim3(DDIM / 32, DDIM / 32), tb>>>(Wk, WkT, DDIM, DDIM);
    transpose_kernel<<<dim3(DDIM / 32, DDIM / 32), tb>>>(Wv, WvT, DDIM, DDIM);

    // QKV: M=4096, N=512, K=512
    {
        dim3 grid(DDIM / 128, N_TOK / 128);
        mma3t_kernel<true><<<grid, 512, GEMM_SMEM_BYTES>>>(x, DDIM, WqT, DDIM, q, DDIM, DDIM, bq, 1.0f);
        mma3t_kernel<true><<<grid, 512, GEMM_SMEM_BYTES>>>(x, DDIM, WkT, DDIM, k, DDIM, DDIM, bk, 1.0f);
        mma3t_kernel<true><<<grid, 512, GEMM_SMEM_BYTES>>>(x, DDIM, WvT, DDIM, v, DDIM, DDIM, bv, 1.0f);
    }

    // kT[n][dd] = (k viewed as [512][4096])^T ; vT = v^T
    transpose_kernel<<<dim3(N_TOK / 32, DDIM / 32), tb>>>(k, kT, DDIM, N_TOK);
    transpose_kernel<<<dim3(DDIM / 32, N_TOK / 32), tb>>>(v, vT, N_TOK, DDIM);

    // Score: M=N=4096, K=512
    {
        dim3 grid(N_TOK / 128, N_TOK / 128);
        mma3t_kernel<false><<<grid, 512, GEMM_SMEM_BYTES>>>(q, DDIM, kT, DDIM, score, N_TOK,
                                                            DDIM, nullptr, inv_sqrt_d);
    }

    // Exact top-k threshold + masked softmax (in-place, radix select)
    topk_softmax_kernel<<<N_TOK, 512>>>(score);

    // Context: M=4096, N=512, K=4096 via split-K=4
    {
        dim3 grid(DDIM / 128, N_TOK / 128);
        for (int sidx = 0; sidx < 4; ++sidx) {
            mma3t_kernel<false><<<grid, 512, GEMM_SMEM_BYTES>>>(
                score + sidx * (N_TOK / 4), N_TOK,
                vT    + sidx * (N_TOK / 4), N_TOK,
                part + (size_t)sidx * N_TOK * DDIM, DDIM,
                N_TOK / 4, nullptr, 1.0f);
        }
        reduce4_kernel<<<(N_TOK * DDIM / 4) / 256, 256>>>(
            (const float4*)(part + 0 * (size_t)N_TOK * DDIM),
            (const float4*)(part + 1 * (size_t)N_TOK * DDIM),
            (const float4*)(part + 2 * (size_t)N_TOK * DDIM),
            (const float4*)(part + 3 * (size_t)N_TOK * DDIM),
            (float4*)out);
    }
}

// round 6
// speedup vs baseline: 1.8865x; 1.0110x over previous
#include <cuda_runtime.h>
#include <cstdint>
#include <math.h>

#define N_TOK 4096
#define DDIM  512
#define KEEP  2048

// ---------------- device scratch (allocation-free) ----------------
__device__ float g_xhi[N_TOK * DDIM];
__device__ float g_xlo[N_TOK * DDIM];
__device__ float g_WThi[3][DDIM * DDIM];
__device__ float g_WTlo[3][DDIM * DDIM];
__device__ float g_qhi[N_TOK * DDIM];
__device__ float g_qlo[N_TOK * DDIM];
__device__ float g_k  [N_TOK * DDIM];
__device__ float g_v  [N_TOK * DDIM];
__device__ float g_kThi[N_TOK * DDIM];
__device__ float g_kTlo[N_TOK * DDIM];
__device__ float g_vThi[N_TOK * DDIM];
__device__ float g_vTlo[N_TOK * DDIM];
__device__ float g_score[(size_t)N_TOK * N_TOK];
__device__ float g_atthi[(size_t)N_TOK * N_TOK];
__device__ float g_attlo[(size_t)N_TOK * N_TOK];
__device__ float g_part[4][N_TOK * DDIM];

// ---------------- helpers ----------------
__device__ __forceinline__ uint32_t smem_u32(const void* p) {
    uint32_t a;
    asm("{ .reg .u64 t; cvta.to.shared.u64 t, %1; cvt.u32.u64 %0, t; }"
        : "=r"(a) : "l"(p));
    return a;
}
__device__ __forceinline__ uint32_t tf32_of(float f) {
    uint32_t u;
    asm("cvt.rna.tf32.f32 %0, %1;" : "=r"(u) : "f"(f));
    return u;
}
__device__ __forceinline__ void split2(float f, float& h, float& l) {
    h = __uint_as_float(tf32_of(f));
    l = __uint_as_float(tf32_of(f - h));
}

#define CP16(dst, src) \
    asm volatile("cp.async.cg.shared.global [%0], [%1], 16;" :: "r"(dst), "l"(src) : "memory")
#define CP_COMMIT() asm volatile("cp.async.commit_group;" ::: "memory")
#define CP_WAIT1()  asm volatile("cp.async.wait_group 1;" ::: "memory")
#define CP_WAIT0()  asm volatile("cp.async.wait_group 0;" ::: "memory")

// 4x (8x8 b16) ldmatrix == 4x (8x4 b32) tiles: thread t gets b32 elem (t/4, t%4)
#define LDSM4(r, a)                                                             \
    asm volatile("ldmatrix.sync.aligned.m8n8.x4.shared.b16 {%0,%1,%2,%3}, [%4];" \
        : "=r"((r)[0]), "=r"((r)[1]), "=r"((r)[2]), "=r"((r)[3]) : "r"(a))

// m16n8k8 tf32 MMA, D += A*B (row.col)
#define MMA8(cc, a, b)                                                          \
    asm volatile("mma.sync.aligned.m16n8k8.row.col.f32.tf32.tf32.f32 "          \
        "{%0,%1,%2,%3}, {%4,%5,%6,%7}, {%8,%9}, {%0,%1,%2,%3};"                 \
        : "+f"((cc)[0]), "+f"((cc)[1]), "+f"((cc)[2]), "+f"((cc)[3])            \
        : "r"((a)[0]), "r"((a)[1]), "r"((a)[2]), "r"((a)[3]),                   \
          "r"((b)[0]), "r"((b)[1]))

// ---------------------------------------------------------------------------
// 3xTF32 mma.sync GEMM on PRE-SPLIT inputs: C = scale*(A @ B^T) (+bias)
// Ahi/Alo [M,K], Bhi/Blo [N,K] row-major, tf32-rounded f32. Block 128x128,
// BK=32, 512 threads / 16 warps 4x4, warp tile 32x32. Mainloop = cp.async +
// ldmatrix + MMA only (no cvt/sub — that was 55% of issue slots in R5).
// Smem: 2 stages x 4 tiles (Ahi,Alo,Bhi,Blo) of 128x36 f32 = 147456 B.
// ---------------------------------------------------------------------------
#define TILE_B    18432                    // 128*36*4
#define STAGE_ALL (4 * TILE_B)             // 73728
#define GEMM_SMEM_BYTES (2 * STAGE_ALL)    // 147456

template<bool BIAS, bool SPLIT_OUT>
__global__ void __launch_bounds__(512, 1)
mma3s_kernel(const float* __restrict__ Ahi, const float* __restrict__ Alo, int lda,
             const float* __restrict__ Bhi, const float* __restrict__ Blo, int ldb,
             float* __restrict__ C, float* __restrict__ Clo, int ldc,
             int K, const float* __restrict__ bias, float scale)
{
    extern __shared__ char sm[];
    const uint32_t smb = smem_u32(sm);

    const int tid  = threadIdx.x;
    const int w    = tid >> 5;
    const int lane = tid & 31;
    const int wm   = w & 3;
    const int wn   = w >> 2;
    const int g    = lane >> 2;
    const int tig  = lane & 3;

    // global loader: thread t -> row t>>2, 8-float quarter (t&3), per tile
    const int lrow = tid >> 2;
    const int lcol = (tid & 3) * 8;
    const float* pAh = Ahi + (size_t)(blockIdx.y * 128 + lrow) * lda + lcol;
    const float* pAl = Alo + (size_t)(blockIdx.y * 128 + lrow) * lda + lcol;
    const float* pBh = Bhi + (size_t)(blockIdx.x * 128 + lrow) * ldb + lcol;
    const float* pBl = Blo + (size_t)(blockIdx.x * 128 + lrow) * ldb + lcol;
    const uint32_t so = (uint32_t)(lrow * 36 + lcol) * 4;

    // ldmatrix per-lane addresses (byte offsets within a stage)
    const int mm = lane >> 3, rr = lane & 7;
    const uint32_t aoff0 = (uint32_t)((wm * 32 + (mm & 1) * 8 + rr) * 36 + (mm >> 1) * 4) * 4;
    const uint32_t aoff1 = aoff0 + 16u * 36u * 4u;
    const uint32_t boff0 = 2u * TILE_B
        + (uint32_t)((wn * 32 + ((mm >> 1) + 0) * 8 + rr) * 36 + (mm & 1) * 4) * 4;
    const uint32_t boff1 = 2u * TILE_B
        + (uint32_t)((wn * 32 + ((mm >> 1) + 2) * 8 + rr) * 36 + (mm & 1) * 4) * 4;

    float c[2][4][4] = {};
    const int nT = K >> 5;

    {
        const uint32_t st = smb;
        CP16(st + so,                       pAh);
        CP16(st + so + 16,                  pAh + 4);
        CP16(st + TILE_B + so,              pAl);
        CP16(st + TILE_B + so + 16,         pAl + 4);
        CP16(st + 2 * TILE_B + so,          pBh);
        CP16(st + 2 * TILE_B + so + 16,     pBh + 4);
        CP16(st + 3 * TILE_B + so,          pBl);
        CP16(st + 3 * TILE_B + so + 16,     pBl + 4);
        CP_COMMIT();
    }

    for (int kt = 0; kt < nT; ++kt) {
        if (kt + 1 < nT) {
            const uint32_t st = smb + ((kt + 1) & 1) * STAGE_ALL;
            const int ko = (kt + 1) * 32;
            CP16(st + so,                   pAh + ko);
            CP16(st + so + 16,              pAh + ko + 4);
            CP16(st + TILE_B + so,          pAl + ko);
            CP16(st + TILE_B + so + 16,     pAl + ko + 4);
            CP16(st + 2 * TILE_B + so,      pBh + ko);
            CP16(st + 2 * TILE_B + so + 16, pBh + ko + 4);
            CP16(st + 3 * TILE_B + so,      pBl + ko);
            CP16(st + 3 * TILE_B + so + 16, pBl + ko + 4);
            CP_COMMIT();
            CP_WAIT1();
        } else {
            CP_WAIT0();
        }
        __syncthreads();

        const uint32_t stb = smb + (kt & 1) * STAGE_ALL;

        #pragma unroll
        for (int ks = 0; ks < 4; ++ks) {
            const uint32_t koff = (uint32_t)ks * 32;

            uint32_t ah[2][4], al[2][4], bh[2][4], bl[2][4];
            LDSM4(ah[0], stb + aoff0 + koff);
            LDSM4(ah[1], stb + aoff1 + koff);
            LDSM4(bh[0], stb + boff0 + koff);
            LDSM4(bh[1], stb + boff1 + koff);
            LDSM4(al[0], stb + TILE_B + aoff0 + koff);
            LDSM4(al[1], stb + TILE_B + aoff1 + koff);
            LDSM4(bl[0], stb + TILE_B + boff0 + koff);
            LDSM4(bl[1], stb + TILE_B + boff1 + koff);

            #pragma unroll
            for (int mi = 0; mi < 2; ++mi)
                #pragma unroll
                for (int ni = 0; ni < 4; ++ni)
                    MMA8(c[mi][ni], ah[mi], bh[ni >> 1] + (ni & 1) * 2);
            #pragma unroll
            for (int mi = 0; mi < 2; ++mi)
                #pragma unroll
                for (int ni = 0; ni < 4; ++ni)
                    MMA8(c[mi][ni], al[mi], bh[ni >> 1] + (ni & 1) * 2);
            #pragma unroll
            for (int mi = 0; mi < 2; ++mi)
                #pragma unroll
                for (int ni = 0; ni < 4; ++ni)
                    MMA8(c[mi][ni], ah[mi], bl[ni >> 1] + (ni & 1) * 2);
        }
        __syncthreads();
    }

    #pragma unroll
    for (int mi = 0; mi < 2; ++mi) {
        const int r0 = blockIdx.y * 128 + wm * 32 + mi * 16 + g;
        #pragma unroll
        for (int ni = 0; ni < 4; ++ni) {
            const int col = blockIdx.x * 128 + wn * 32 + ni * 8 + tig * 2;
            float vv[4];
            vv[0] = c[mi][ni][0] * scale; vv[1] = c[mi][ni][1] * scale;
            vv[2] = c[mi][ni][2] * scale; vv[3] = c[mi][ni][3] * scale;
            if (BIAS) {
                const float b0 = bias[col], b1 = bias[col + 1];
                vv[0] += b0; vv[1] += b1; vv[2] += b0; vv[3] += b1;
            }
            if (SPLIT_OUT) {
                float h[4], l[4];
                #pragma unroll
                for (int e = 0; e < 4; ++e) split2(vv[e], h[e], l[e]);
                *reinterpret_cast<float2*>(C   + (size_t)r0 * ldc + col)        = make_float2(h[0], h[1]);
                *reinterpret_cast<float2*>(C   + (size_t)(r0 + 8) * ldc + col)  = make_float2(h[2], h[3]);
                *reinterpret_cast<float2*>(Clo + (size_t)r0 * ldc + col)        = make_float2(l[0], l[1]);
                *reinterpret_cast<float2*>(Clo + (size_t)(r0 + 8) * ldc + col)  = make_float2(l[2], l[3]);
            } else {
                *reinterpret_cast<float2*>(C + (size_t)r0 * ldc + col)       = make_float2(vv[0], vv[1]);
                *reinterpret_cast<float2*>(C + (size_t)(r0 + 8) * ldc + col) = make_float2(vv[2], vv[3]);
            }
        }
    }
}

// ---------------------------------------------------------------------------
// Elementwise tf32 split: in -> (hi, lo)
// ---------------------------------------------------------------------------
__global__ void __launch_bounds__(256)
split_kernel(const float* __restrict__ in, float* __restrict__ hi,
             float* __restrict__ lo)
{
    const int i = blockIdx.x * blockDim.x + threadIdx.x;
    float h, l;
    split2(in[i], h, l);
    hi[i] = h;
    lo[i] = l;
}

// ---------------------------------------------------------------------------
// 32x32 tiled transpose with tf32 split: in [R][C] -> hi/lo [C][R]
// ---------------------------------------------------------------------------
__global__ void __launch_bounds__(256)
transpose_split_kernel(const float* __restrict__ in, float* __restrict__ hi,
                       float* __restrict__ lo, int R, int C)
{
    __shared__ float t[32][33];
    const int bx = blockIdx.x * 32, by = blockIdx.y * 32;
    const int tx = threadIdx.x, ty = threadIdx.y;
    #pragma unroll
    for (int j = 0; j < 32; j += 8)
        t[ty + j][tx] = in[(size_t)(by + ty + j) * C + bx + tx];
    __syncthreads();
    #pragma unroll
    for (int j = 0; j < 32; j += 8) {
        float h, l;
        split2(t[tx][ty + j], h, l);
        hi[(size_t)(bx + ty + j) * R + by + tx] = h;
        lo[(size_t)(bx + ty + j) * R + by + tx] = l;
    }
}

// ---------------------------------------------------------------------------
// Exact per-row top-k (4-pass radix select on order-preserving bits) +
// masked softmax; writes attn pre-split (hi, lo). One block (512 thr)/row.
// ---------------------------------------------------------------------------
__global__ void __launch_bounds__(512)
topk_softmax_kernel(const float* __restrict__ score,
                    float* __restrict__ atthi, float* __restrict__ attlo)
{
    __shared__ uint32_t s[N_TOK];
    __shared__ uint32_t hist[256];
    __shared__ uint32_t sh_sel[2];
    __shared__ float red[16];

    const int tid = threadIdx.x;
    const float* row = score + (size_t)blockIdx.x * N_TOK;

    float orig[8];
    uint32_t su[8];
    #pragma unroll
    for (int cidx = 0; cidx < 8; ++cidx) {
        const float f = row[tid + cidx * 512];
        orig[cidx] = f;
        uint32_t u = __float_as_uint(f);
        u ^= (uint32_t)(((int32_t)u) >> 31) | 0x80000000u;
        su[cidx] = u;
        s[tid + cidx * 512] = u;
    }

    uint32_t prefix = 0, rank = KEEP;
    #pragma unroll
    for (int pass = 0; pass < 4; ++pass) {
        const int shift   = 24 - pass * 8;
        const int hishift = (pass == 0) ? 0 : (shift + 8);
        if (tid < 256) hist[tid] = 0;
        __syncthreads();
        #pragma unroll
        for (int cidx = 0; cidx < 8; ++cidx) {
            const uint32_t u = s[tid + cidx * 512];
            const bool match = (pass == 0) || (((u ^ prefix) >> hishift) == 0);
            if (match) atomicAdd(&hist[(u >> shift) & 0xFFu], 1u);
        }
        __syncthreads();
        if (tid < 32) {
            uint32_t h[8], sum = 0;
            #pragma unroll
            for (int i = 0; i < 8; ++i) {
                h[i] = hist[255 - (tid * 8 + i)];
                sum += h[i];
            }
            uint32_t inc = sum;
            #pragma unroll
            for (int o = 1; o < 32; o <<= 1) {
                const uint32_t t = __shfl_up_sync(0xffffffffu, inc, o);
                if (tid >= o) inc += t;
            }
            const uint32_t exc = inc - sum;
            if (exc < rank && rank <= inc) {
                uint32_t cum = exc;
                #pragma unroll
                for (int i = 0; i < 8; ++i) {
                    cum += h[i];
                    if (cum >= rank) {
                        sh_sel[0] = prefix | ((uint32_t)(255 - (tid * 8 + i)) << shift);
                        sh_sel[1] = rank - (cum - h[i]);
                        break;
                    }
                }
            }
        }
        __syncthreads();
        prefix = sh_sel[0];
        rank   = sh_sel[1];
        __syncthreads();
    }
    const uint32_t thr_u = prefix;

    float m[8];
    float lmax = 0.0f;
    #pragma unroll
    for (int cidx = 0; cidx < 8; ++cidx) {
        m[cidx] = (su[cidx] > thr_u) ? orig[cidx] : 0.0f;
        lmax = fmaxf(lmax, m[cidx]);
    }
    #pragma unroll
    for (int o = 16; o; o >>= 1)
        lmax = fmaxf(lmax, __shfl_xor_sync(0xffffffffu, lmax, o));
    if ((tid & 31) == 0) red[tid >> 5] = lmax;
    __syncthreads();
    float gmax;
    {
        float v2 = red[tid & 15];
        #pragma unroll
        for (int o = 8; o; o >>= 1)
            v2 = fmaxf(v2, __shfl_xor_sync(0xffffffffu, v2, o));
        gmax = v2;
    }
    __syncthreads();

    float e[8];
    float lsum = 0.0f;
    #pragma unroll
    for (int cidx = 0; cidx < 8; ++cidx) {
        e[cidx] = expf(m[cidx] - gmax);
        lsum += e[cidx];
    }
    #pragma unroll
    for (int o = 16; o; o >>= 1)
        lsum += __shfl_xor_sync(0xffffffffu, lsum, o);
    if ((tid & 31) == 0) red[tid >> 5] = lsum;
    __syncthreads();
    float gsum;
    {
        float v2 = red[tid & 15];
        #pragma unroll
        for (int o = 8; o; o >>= 1)
            v2 += __shfl_xor_sync(0xffffffffu, v2, o);
        gsum = v2;
    }

    const float inv = 1.0f / gsum;
    #pragma unroll
    for (int cidx = 0; cidx < 8; ++cidx) {
        float h, l;
        split2(e[cidx] * inv, h, l);
        atthi[(size_t)blockIdx.x * N_TOK + tid + cidx * 512] = h;
        attlo[(size_t)blockIdx.x * N_TOK + tid + cidx * 512] = l;
    }
}

// ---------------------------------------------------------------------------
// Deterministic 4-way split-K reduce
// ---------------------------------------------------------------------------
__global__ void __launch_bounds__(256)
reduce4_kernel(const float4* __restrict__ p0, const float4* __restrict__ p1,
               const float4* __restrict__ p2, const float4* __restrict__ p3,
               float4* __restrict__ out)
{
    const int i = blockIdx.x * blockDim.x + threadIdx.x;
    float4 a = p0[i], b = p1[i], c = p2[i], d = p3[i];
    float4 o;
    o.x = ((a.x + b.x) + c.x) + d.x;
    o.y = ((a.y + b.y) + c.y) + d.y;
    o.z = ((a.z + b.z) + c.z) + d.z;
    o.w = ((a.w + b.w) + c.w) + d.w;
    out[i] = o;
}

// ---------------------------------------------------------------------------
extern "C" void kernel_launch(void* const* d_in, const int* in_sizes, int n_in,
                              void* d_out, int out_size)
{
    const float* x  = (const float*)d_in[0];
    const float* Wq = (const float*)d_in[1];
    const float* bq = (const float*)d_in[2];
    const float* Wk = (const float*)d_in[3];
    const float* bk = (const float*)d_in[4];
    const float* Wv = (const float*)d_in[5];
    const float* bv = (const float*)d_in[6];
    float* out = (float*)d_out;

    float *xhi, *xlo, *WThi, *WTlo, *qhi, *qlo, *k, *v;
    float *kThi, *kTlo, *vThi, *vTlo, *score, *atthi, *attlo, *part;
    cudaGetSymbolAddress((void**)&xhi,   g_xhi);
    cudaGetSymbolAddress((void**)&xlo,   g_xlo);
    cudaGetSymbolAddress((void**)&WThi,  g_WThi);
    cudaGetSymbolAddress((void**)&WTlo,  g_WTlo);
    cudaGetSymbolAddress((void**)&qhi,   g_qhi);
    cudaGetSymbolAddress((void**)&qlo,   g_qlo);
    cudaGetSymbolAddress((void**)&k,     g_k);
    cudaGetSymbolAddress((void**)&v,     g_v);
    cudaGetSymbolAddress((void**)&kThi,  g_kThi);
    cudaGetSymbolAddress((void**)&kTlo,  g_kTlo);
    cudaGetSymbolAddress((void**)&vThi,  g_vThi);
    cudaGetSymbolAddress((void**)&vTlo,  g_vTlo);
    cudaGetSymbolAddress((void**)&score, g_score);
    cudaGetSymbolAddress((void**)&atthi, g_atthi);
    cudaGetSymbolAddress((void**)&attlo, g_attlo);
    cudaGetSymbolAddress((void**)&part,  g_part);

    cudaFuncSetAttribute(mma3s_kernel<true, true>,
                         cudaFuncAttributeMaxDynamicSharedMemorySize, GEMM_SMEM_BYTES);
    cudaFuncSetAttribute(mma3s_kernel<true, false>,
                         cudaFuncAttributeMaxDynamicSharedMemorySize, GEMM_SMEM_BYTES);
    cudaFuncSetAttribute(mma3s_kernel<false, false>,
                         cudaFuncAttributeMaxDynamicSharedMemorySize, GEMM_SMEM_BYTES);

    const float inv_sqrt_d = 1.0f / sqrtf((float)DDIM);
    const dim3 tb(32, 8);

    // Pre-split x; transpose+split weights: W [in,out] -> WT [out,in] hi/lo
    split_kernel<<<(N_TOK * DDIM) / 256, 256>>>(x, xhi, xlo);
    transpose_split_kernel<<<dim3(DDIM / 32, DDIM / 32), tb>>>(Wq, WThi + 0 * DDIM * DDIM, WTlo + 0 * DDIM * DDIM, DDIM, DDIM);
    transpose_split_kernel<<<dim3(DDIM / 32, DDIM / 32), tb>>>(Wk, WThi + 1 * DDIM * DDIM, WTlo + 1 * DDIM * DDIM, DDIM, DDIM);
    transpose_split_kernel<<<dim3(DDIM / 32, DDIM / 32), tb>>>(Wv, WThi + 2 * DDIM * DDIM, WTlo + 2 * DDIM * DDIM, DDIM, DDIM);

    // QKV: M=4096, N=512, K=512. q emitted pre-split; k, v plain.
    {
        dim3 grid(DDIM / 128, N_TOK / 128);
        mma3s_kernel<true, true><<<grid, 512, GEMM_SMEM_BYTES>>>(
            xhi, xlo, DDIM, WThi + 0 * DDIM * DDIM, WTlo + 0 * DDIM * DDIM, DDIM,
            qhi, qlo, DDIM, DDIM, bq, 1.0f);
        mma3s_kernel<true, false><<<grid, 512, GEMM_SMEM_BYTES>>>(
            xhi, xlo, DDIM, WThi + 1 * DDIM * DDIM, WTlo + 1 * DDIM * DDIM, DDIM,
            k, nullptr, DDIM, DDIM, bk, 1.0f);
        mma3s_kernel<true, false><<<grid, 512, GEMM_SMEM_BYTES>>>(
            xhi, xlo, DDIM, WThi + 2 * DDIM * DDIM, WTlo + 2 * DDIM * DDIM, DDIM,
            v, nullptr, DDIM, DDIM, bv, 1.0f);
    }

    // kT[n][dd] = (k viewed as [512][4096])^T, split; vT = v^T, split
    transpose_split_kernel<<<dim3(N_TOK / 32, DDIM / 32), tb>>>(k, kThi, kTlo, DDIM, N_TOK);
    transpose_split_kernel<<<dim3(DDIM / 32, N_TOK / 32), tb>>>(v, vThi, vTlo, N_TOK, DDIM);

    // Score: M=N=4096, K=512
    {
        dim3 grid(N_TOK / 128, N_TOK / 128);
        mma3s_kernel<false, false><<<grid, 512, GEMM_SMEM_BYTES>>>(
            qhi, qlo, DDIM, kThi, kTlo, DDIM, score, nullptr, N_TOK,
            DDIM, nullptr, inv_sqrt_d);
    }

    // Exact top-k + masked softmax; attn emitted pre-split
    topk_softmax_kernel<<<N_TOK, 512>>>(score, atthi, attlo);

    // Context: M=4096, N=512, K=4096 via split-K=4
    {
        dim3 grid(DDIM / 128, N_TOK / 128);
        for (int sidx = 0; sidx < 4; ++sidx) {
            mma3s_kernel<false, false><<<grid, 512, GEMM_SMEM_BYTES>>>(
                atthi + sidx * (N_TOK / 4), attlo + sidx * (N_TOK / 4), N_TOK,
                vThi  + sidx * (N_TOK / 4), vTlo  + sidx * (N_TOK / 4), N_TOK,
                part + (size_t)sidx * N_TOK * DDIM, nullptr, DDIM,
                N_TOK / 4, nullptr, 1.0f);
        }
        reduce4_kernel<<<(N_TOK * DDIM / 4) / 256, 256>>>(
            (const float4*)(part + 0 * (size_t)N_TOK * DDIM),
            (const float4*)(part + 1 * (size_t)N_TOK * DDIM),
            (const float4*)(part + 2 * (size_t)N_TOK * DDIM),
            (const float4*)(part + 3 * (size_t)N_TOK * DDIM),
            (float4*)out);
    }
}

// round 7
// speedup vs baseline: 3.3845x; 1.7941x over previous
#include <cuda_runtime.h>
#include <cuda_bf16.h>
#include <cstdint>
#include <math.h>

#define N_TOK 4096
#define DDIM  512
#define KEEP  2048

// ---------------- device scratch (uint4 for 16B alignment) ----------------
// bf16 buffers sized in uint4 (8 bf16 per uint4)
__device__ uint4 g_xhi [N_TOK * DDIM / 8];
__device__ uint4 g_xlo [N_TOK * DDIM / 8];
__device__ uint4 g_WThi[3 * DDIM * DDIM / 8];
__device__ uint4 g_WTlo[3 * DDIM * DDIM / 8];
__device__ uint4 g_qhi [N_TOK * DDIM / 8];
__device__ uint4 g_qlo [N_TOK * DDIM / 8];
__device__ uint4 g_kThi[N_TOK * DDIM / 8];
__device__ uint4 g_kTlo[N_TOK * DDIM / 8];
__device__ uint4 g_vThi[N_TOK * DDIM / 8];
__device__ uint4 g_vTlo[N_TOK * DDIM / 8];
__device__ uint4 g_atthi[(size_t)N_TOK * N_TOK / 8];
__device__ uint4 g_attlo[(size_t)N_TOK * N_TOK / 8];
// f32 buffers
__device__ float g_k[N_TOK * DDIM];
__device__ float g_v[N_TOK * DDIM];
__device__ float g_score[(size_t)N_TOK * N_TOK];
__device__ float g_part[4][N_TOK * DDIM];

typedef __nv_bfloat16 bf16;

// ---------------- helpers ----------------
__device__ __forceinline__ uint32_t smem_u32(const void* p) {
    uint32_t a;
    asm("{ .reg .u64 t; cvta.to.shared.u64 t, %1; cvt.u32.u64 %0, t; }"
        : "=r"(a) : "l"(p));
    return a;
}
__device__ __forceinline__ void split_bf(float f, bf16& h, bf16& l) {
    h = __float2bfloat16_rn(f);
    l = __float2bfloat16_rn(f - __bfloat162float(h));
}

#define CP16(dst, src) \
    asm volatile("cp.async.cg.shared.global [%0], [%1], 16;" :: "r"(dst), "l"(src) : "memory")
#define CP_COMMIT() asm volatile("cp.async.commit_group;" ::: "memory")
#define CP_WAIT1()  asm volatile("cp.async.wait_group 1;" ::: "memory")
#define CP_WAIT0()  asm volatile("cp.async.wait_group 0;" ::: "memory")

#define LDSM4(r, a)                                                             \
    asm volatile("ldmatrix.sync.aligned.m8n8.x4.shared.b16 {%0,%1,%2,%3}, [%4];" \
        : "=r"((r)[0]), "=r"((r)[1]), "=r"((r)[2]), "=r"((r)[3]) : "r"(a))

// m16n8k16 bf16 MMA, D += A*B (row.col), f32 accumulate
#define MMA16(cc, a, b)                                                         \
    asm volatile("mma.sync.aligned.m16n8k16.row.col.f32.bf16.bf16.f32 "         \
        "{%0,%1,%2,%3}, {%4,%5,%6,%7}, {%8,%9}, {%0,%1,%2,%3};"                 \
        : "+f"((cc)[0]), "+f"((cc)[1]), "+f"((cc)[2]), "+f"((cc)[3])            \
        : "r"((a)[0]), "r"((a)[1]), "r"((a)[2]), "r"((a)[3]),                   \
          "r"((b)[0]), "r"((b)[1]))

// ---------------------------------------------------------------------------
// 3xBF16 mma.sync GEMM body: C = scale*(A @ B^T) (+bias)
// Ahi/Alo [M,K], Bhi/Blo [N,K] bf16 row-major. Block 128x128, BK=64,
// 512 threads / 16 warps 4x4, warp tile 32x32. Smem: 2 stages x 4 tiles of
// 128 rows x 144B pitch (128B data) = 147456 B total.
// ---------------------------------------------------------------------------
#define TILE_B    18432                    // 128 * 144
#define STAGE_ALL (4 * TILE_B)             // 73728
#define GEMM_SMEM_BYTES (2 * STAGE_ALL)    // 147456

template<bool BIAS, bool SPLIT_OUT>
__device__ __forceinline__ void gemm_body(
    const bf16* __restrict__ Ahi, const bf16* __restrict__ Alo, int lda,
    const bf16* __restrict__ Bhi, const bf16* __restrict__ Blo, int ldb,
    float* __restrict__ C, bf16* __restrict__ Chi, bf16* __restrict__ Clo, int ldc,
    int K, const float* __restrict__ bias, float scale,
    int bx, int by, char* sm)
{
    const uint32_t smb = smem_u32(sm);

    const int tid  = threadIdx.x;
    const int w    = tid >> 5;
    const int lane = tid & 31;
    const int wm   = w & 3;
    const int wn   = w >> 2;
    const int g    = lane >> 2;
    const int tig  = lane & 3;

    // global loader: thread t -> row t>>2, 32B chunk (t&3)
    const int lrow = tid >> 2;
    const int lch  = tid & 3;
    const bf16* pAh = Ahi + (size_t)(by * 128 + lrow) * lda + lch * 16;
    const bf16* pAl = Alo + (size_t)(by * 128 + lrow) * lda + lch * 16;
    const bf16* pBh = Bhi + (size_t)(bx * 128 + lrow) * ldb + lch * 16;
    const bf16* pBl = Blo + (size_t)(bx * 128 + lrow) * ldb + lch * 16;
    const uint32_t so = (uint32_t)lrow * 144 + lch * 32;

    // ldmatrix lane offsets (bytes within a stage)
    const int l7 = lane & 7;
    const uint32_t aoff0 = (uint32_t)(wm * 32 + ((lane >> 3) & 1) * 8 + l7) * 144
                         + (uint32_t)(lane >> 4) * 16;
    const uint32_t aoff1 = aoff0 + 16u * 144u;
    const uint32_t boff0 = 2u * TILE_B
                         + (uint32_t)(wn * 32 + (lane >> 4) * 8 + l7) * 144
                         + (uint32_t)((lane >> 3) & 1) * 16;
    const uint32_t boff1 = boff0 + 16u * 144u;

    float c[2][4][4] = {};
    const int nT = K >> 6;

    {
        const uint32_t st = smb;
        CP16(st + so,                   pAh);
        CP16(st + so + 16,              pAh + 8);
        CP16(st + TILE_B + so,          pAl);
        CP16(st + TILE_B + so + 16,     pAl + 8);
        CP16(st + 2 * TILE_B + so,      pBh);
        CP16(st + 2 * TILE_B + so + 16, pBh + 8);
        CP16(st + 3 * TILE_B + so,      pBl);
        CP16(st + 3 * TILE_B + so + 16, pBl + 8);
        CP_COMMIT();
    }

    for (int kt = 0; kt < nT; ++kt) {
        if (kt + 1 < nT) {
            const uint32_t st = smb + ((kt + 1) & 1) * STAGE_ALL;
            const int ko = (kt + 1) * 64;
            CP16(st + so,                   pAh + ko);
            CP16(st + so + 16,              pAh + ko + 8);
            CP16(st + TILE_B + so,          pAl + ko);
            CP16(st + TILE_B + so + 16,     pAl + ko + 8);
            CP16(st + 2 * TILE_B + so,      pBh + ko);
            CP16(st + 2 * TILE_B + so + 16, pBh + ko + 8);
            CP16(st + 3 * TILE_B + so,      pBl + ko);
            CP16(st + 3 * TILE_B + so + 16, pBl + ko + 8);
            CP_COMMIT();
            CP_WAIT1();
        } else {
            CP_WAIT0();
        }
        __syncthreads();

        const uint32_t stb = smb + (kt & 1) * STAGE_ALL;

        #pragma unroll
        for (int ks = 0; ks < 4; ++ks) {
            const uint32_t koff = (uint32_t)ks * 32;   // 16 bf16 = 32B per k-step

            uint32_t ah[2][4], al[2][4], bh[2][4], bl[2][4];
            LDSM4(ah[0], stb + aoff0 + koff);
            LDSM4(ah[1], stb + aoff1 + koff);
            LDSM4(bh[0], stb + boff0 + koff);
            LDSM4(bh[1], stb + boff1 + koff);
            LDSM4(al[0], stb + TILE_B + aoff0 + koff);
            LDSM4(al[1], stb + TILE_B + aoff1 + koff);
            LDSM4(bl[0], stb + TILE_B + boff0 + koff);
            LDSM4(bl[1], stb + TILE_B + boff1 + koff);

            #pragma unroll
            for (int mi = 0; mi < 2; ++mi)
                #pragma unroll
                for (int ni = 0; ni < 4; ++ni)
                    MMA16(c[mi][ni], ah[mi], bh[ni >> 1] + (ni & 1) * 2);
            #pragma unroll
            for (int mi = 0; mi < 2; ++mi)
                #pragma unroll
                for (int ni = 0; ni < 4; ++ni)
                    MMA16(c[mi][ni], al[mi], bh[ni >> 1] + (ni & 1) * 2);
            #pragma unroll
            for (int mi = 0; mi < 2; ++mi)
                #pragma unroll
                for (int ni = 0; ni < 4; ++ni)
                    MMA16(c[mi][ni], ah[mi], bl[ni >> 1] + (ni & 1) * 2);
        }
        __syncthreads();
    }

    #pragma unroll
    for (int mi = 0; mi < 2; ++mi) {
        const int r0 = by * 128 + wm * 32 + mi * 16 + g;
        #pragma unroll
        for (int ni = 0; ni < 4; ++ni) {
            const int col = bx * 128 + wn * 32 + ni * 8 + tig * 2;
            float vv[4];
            vv[0] = c[mi][ni][0] * scale; vv[1] = c[mi][ni][1] * scale;
            vv[2] = c[mi][ni][2] * scale; vv[3] = c[mi][ni][3] * scale;
            if (BIAS) {
                const float b0 = bias[col], b1 = bias[col + 1];
                vv[0] += b0; vv[1] += b1; vv[2] += b0; vv[3] += b1;
            }
            if (SPLIT_OUT) {
                bf16 h[4], l[4];
                #pragma unroll
                for (int e = 0; e < 4; ++e) split_bf(vv[e], h[e], l[e]);
                __nv_bfloat162 t2;
                t2.x = h[0]; t2.y = h[1];
                *reinterpret_cast<__nv_bfloat162*>(Chi + (size_t)r0 * ldc + col) = t2;
                t2.x = h[2]; t2.y = h[3];
                *reinterpret_cast<__nv_bfloat162*>(Chi + (size_t)(r0 + 8) * ldc + col) = t2;
                t2.x = l[0]; t2.y = l[1];
                *reinterpret_cast<__nv_bfloat162*>(Clo + (size_t)r0 * ldc + col) = t2;
                t2.x = l[2]; t2.y = l[3];
                *reinterpret_cast<__nv_bfloat162*>(Clo + (size_t)(r0 + 8) * ldc + col) = t2;
            } else {
                *reinterpret_cast<float2*>(C + (size_t)r0 * ldc + col)       = make_float2(vv[0], vv[1]);
                *reinterpret_cast<float2*>(C + (size_t)(r0 + 8) * ldc + col) = make_float2(vv[2], vv[3]);
            }
        }
    }
}

// Generic single-GEMM kernel (score)
template<bool BIAS, bool SPLIT_OUT>
__global__ void __launch_bounds__(512, 1)
mma_bf16_kernel(const bf16* __restrict__ Ahi, const bf16* __restrict__ Alo, int lda,
                const bf16* __restrict__ Bhi, const bf16* __restrict__ Blo, int ldb,
                float* __restrict__ C, bf16* __restrict__ Chi, bf16* __restrict__ Clo,
                int ldc, int K, const float* __restrict__ bias, float scale)
{
    extern __shared__ char sm[];
    gemm_body<BIAS, SPLIT_OUT>(Ahi, Alo, lda, Bhi, Blo, ldb, C, Chi, Clo, ldc,
                               K, bias, scale, blockIdx.x, blockIdx.y, sm);
}

// Merged QKV: grid (4, 32, 3); z=0 -> q (bf16 split out), z=1 -> k, z=2 -> v
__global__ void __launch_bounds__(512, 1)
qkv_kernel(const bf16* __restrict__ xhi, const bf16* __restrict__ xlo,
           const bf16* __restrict__ WThi, const bf16* __restrict__ WTlo,
           const float* __restrict__ bq, const float* __restrict__ bk,
           const float* __restrict__ bv,
           bf16* __restrict__ qhi, bf16* __restrict__ qlo,
           float* __restrict__ k, float* __restrict__ v)
{
    extern __shared__ char sm[];
    const int z = blockIdx.z;
    const bf16* Wh = WThi + (size_t)z * DDIM * DDIM;
    const bf16* Wl = WTlo + (size_t)z * DDIM * DDIM;
    if (z == 0)
        gemm_body<true, true>(xhi, xlo, DDIM, Wh, Wl, DDIM, nullptr, qhi, qlo,
                              DDIM, DDIM, bq, 1.0f, blockIdx.x, blockIdx.y, sm);
    else if (z == 1)
        gemm_body<true, false>(xhi, xlo, DDIM, Wh, Wl, DDIM, k, nullptr, nullptr,
                               DDIM, DDIM, bk, 1.0f, blockIdx.x, blockIdx.y, sm);
    else
        gemm_body<true, false>(xhi, xlo, DDIM, Wh, Wl, DDIM, v, nullptr, nullptr,
                               DDIM, DDIM, bv, 1.0f, blockIdx.x, blockIdx.y, sm);
}

// Merged context split-K: grid (4, 32, 4); z = K-slice
__global__ void __launch_bounds__(512, 1)
ctx_kernel(const bf16* __restrict__ atthi, const bf16* __restrict__ attlo,
           const bf16* __restrict__ vThi, const bf16* __restrict__ vTlo,
           float* __restrict__ part)
{
    extern __shared__ char sm[];
    const int z = blockIdx.z;
    gemm_body<false, false>(atthi + z * (N_TOK / 4), attlo + z * (N_TOK / 4), N_TOK,
                            vThi + z * (N_TOK / 4), vTlo + z * (N_TOK / 4), N_TOK,
                            part + (size_t)z * N_TOK * DDIM, nullptr, nullptr, DDIM,
                            N_TOK / 4, nullptr, 1.0f, blockIdx.x, blockIdx.y, sm);
}

// ---------------------------------------------------------------------------
// Elementwise bf16 split
// ---------------------------------------------------------------------------
__global__ void __launch_bounds__(256)
split_kernel(const float* __restrict__ in, bf16* __restrict__ hi, bf16* __restrict__ lo)
{
    const int i = blockIdx.x * blockDim.x + threadIdx.x;
    bf16 h, l;
    split_bf(in[i], h, l);
    hi[i] = h;
    lo[i] = l;
}

// ---------------------------------------------------------------------------
// 32x32 tiled transpose with bf16 split: in [R][C] f32 -> hi/lo [C][R] bf16
// ---------------------------------------------------------------------------
__global__ void __launch_bounds__(256)
transpose_split_kernel(const float* __restrict__ in, bf16* __restrict__ hi,
                       bf16* __restrict__ lo, int R, int C)
{
    __shared__ float t[32][33];
    const int bx = blockIdx.x * 32, by = blockIdx.y * 32;
    const int tx = threadIdx.x, ty = threadIdx.y;
    #pragma unroll
    for (int j = 0; j < 32; j += 8)
        t[ty + j][tx] = in[(size_t)(by + ty + j) * C + bx + tx];
    __syncthreads();
    #pragma unroll
    for (int j = 0; j < 32; j += 8) {
        bf16 h, l;
        split_bf(t[tx][ty + j], h, l);
        hi[(size_t)(bx + ty + j) * R + by + tx] = h;
        lo[(size_t)(bx + ty + j) * R + by + tx] = l;
    }
}

// ---------------------------------------------------------------------------
// Exact per-row top-k (4-pass radix select on order-preserving bits) +
// masked softmax; emits attn pre-split to bf16 hi/lo. One block (512 thr)/row.
// ---------------------------------------------------------------------------
__global__ void __launch_bounds__(512)
topk_softmax_kernel(const float* __restrict__ score,
                    bf16* __restrict__ atthi, bf16* __restrict__ attlo)
{
    __shared__ uint32_t s[N_TOK];
    __shared__ uint32_t hist[256];
    __shared__ uint32_t sh_sel[2];
    __shared__ float red[16];

    const int tid = threadIdx.x;
    const float* row = score + (size_t)blockIdx.x * N_TOK;

    float orig[8];
    uint32_t su[8];
    #pragma unroll
    for (int cidx = 0; cidx < 8; ++cidx) {
        const float f = row[tid + cidx * 512];
        orig[cidx] = f;
        uint32_t u = __float_as_uint(f);
        u ^= (uint32_t)(((int32_t)u) >> 31) | 0x80000000u;
        su[cidx] = u;
        s[tid + cidx * 512] = u;
    }

    uint32_t prefix = 0, rank = KEEP;
    #pragma unroll
    for (int pass = 0; pass < 4; ++pass) {
        const int shift   = 24 - pass * 8;
        const int hishift = (pass == 0) ? 0 : (shift + 8);
        if (tid < 256) hist[tid] = 0;
        __syncthreads();
        #pragma unroll
        for (int cidx = 0; cidx < 8; ++cidx) {
            const uint32_t u = s[tid + cidx * 512];
            const bool match = (pass == 0) || (((u ^ prefix) >> hishift) == 0);
            if (match) atomicAdd(&hist[(u >> shift) & 0xFFu], 1u);
        }
        __syncthreads();
        if (tid < 32) {
            uint32_t h[8], sum = 0;
            #pragma unroll
            for (int i = 0; i < 8; ++i) {
                h[i] = hist[255 - (tid * 8 + i)];
                sum += h[i];
            }
            uint32_t inc = sum;
            #pragma unroll
            for (int o = 1; o < 32; o <<= 1) {
                const uint32_t t = __shfl_up_sync(0xffffffffu, inc, o);
                if (tid >= o) inc += t;
            }
            const uint32_t exc = inc - sum;
            if (exc < rank && rank <= inc) {
                uint32_t cum = exc;
                #pragma unroll
                for (int i = 0; i < 8; ++i) {
                    cum += h[i];
                    if (cum >= rank) {
                        sh_sel[0] = prefix | ((uint32_t)(255 - (tid * 8 + i)) << shift);
                        sh_sel[1] = rank - (cum - h[i]);
                        break;
                    }
                }
            }
        }
        __syncthreads();
        prefix = sh_sel[0];
        rank   = sh_sel[1];
        __syncthreads();
    }
    const uint32_t thr_u = prefix;

    float m[8];
    float lmax = 0.0f;
    #pragma unroll
    for (int cidx = 0; cidx < 8; ++cidx) {
        m[cidx] = (su[cidx] > thr_u) ? orig[cidx] : 0.0f;
        lmax = fmaxf(lmax, m[cidx]);
    }
    #pragma unroll
    for (int o = 16; o; o >>= 1)
        lmax = fmaxf(lmax, __shfl_xor_sync(0xffffffffu, lmax, o));
    if ((tid & 31) == 0) red[tid >> 5] = lmax;
    __syncthreads();
    float gmax;
    {
        float v2 = red[tid & 15];
        #pragma unroll
        for (int o = 8; o; o >>= 1)
            v2 = fmaxf(v2, __shfl_xor_sync(0xffffffffu, v2, o));
        gmax = v2;
    }
    __syncthreads();

    float e[8];
    float lsum = 0.0f;
    #pragma unroll
    for (int cidx = 0; cidx < 8; ++cidx) {
        e[cidx] = expf(m[cidx] - gmax);
        lsum += e[cidx];
    }
    #pragma unroll
    for (int o = 16; o; o >>= 1)
        lsum += __shfl_xor_sync(0xffffffffu, lsum, o);
    if ((tid & 31) == 0) red[tid >> 5] = lsum;
    __syncthreads();
    float gsum;
    {
        float v2 = red[tid & 15];
        #pragma unroll
        for (int o = 8; o; o >>= 1)
            v2 += __shfl_xor_sync(0xffffffffu, v2, o);
        gsum = v2;
    }

    const float inv = 1.0f / gsum;
    #pragma unroll
    for (int cidx = 0; cidx < 8; ++cidx) {
        bf16 h, l;
        split_bf(e[cidx] * inv, h, l);
        atthi[(size_t)blockIdx.x * N_TOK + tid + cidx * 512] = h;
        attlo[(size_t)blockIdx.x * N_TOK + tid + cidx * 512] = l;
    }
}

// ---------------------------------------------------------------------------
// Deterministic 4-way split-K reduce
// ---------------------------------------------------------------------------
__global__ void __launch_bounds__(256)
reduce4_kernel(const float4* __restrict__ p0, const float4* __restrict__ p1,
               const float4* __restrict__ p2, const float4* __restrict__ p3,
               float4* __restrict__ out)
{
    const int i = blockIdx.x * blockDim.x + threadIdx.x;
    float4 a = p0[i], b = p1[i], c = p2[i], d = p3[i];
    float4 o;
    o.x = ((a.x + b.x) + c.x) + d.x;
    o.y = ((a.y + b.y) + c.y) + d.y;
    o.z = ((a.z + b.z) + c.z) + d.z;
    o.w = ((a.w + b.w) + c.w) + d.w;
    out[i] = o;
}

// ---------------------------------------------------------------------------
extern "C" void kernel_launch(void* const* d_in, const int* in_sizes, int n_in,
                              void* d_out, int out_size)
{
    const float* x  = (const float*)d_in[0];
    const float* Wq = (const float*)d_in[1];
    const float* bq = (const float*)d_in[2];
    const float* Wk = (const float*)d_in[3];
    const float* bk = (const float*)d_in[4];
    const float* Wv = (const float*)d_in[5];
    const float* bv = (const float*)d_in[6];
    float* out = (float*)d_out;

    bf16 *xhi, *xlo, *WThi, *WTlo, *qhi, *qlo, *kThi, *kTlo, *vThi, *vTlo, *atthi, *attlo;
    float *k, *v, *score, *part;
    cudaGetSymbolAddress((void**)&xhi,   g_xhi);
    cudaGetSymbolAddress((void**)&xlo,   g_xlo);
    cudaGetSymbolAddress((void**)&WThi,  g_WThi);
    cudaGetSymbolAddress((void**)&WTlo,  g_WTlo);
    cudaGetSymbolAddress((void**)&qhi,   g_qhi);
    cudaGetSymbolAddress((void**)&qlo,   g_qlo);
    cudaGetSymbolAddress((void**)&kThi,  g_kThi);
    cudaGetSymbolAddress((void**)&kTlo,  g_kTlo);
    cudaGetSymbolAddress((void**)&vThi,  g_vThi);
    cudaGetSymbolAddress((void**)&vTlo,  g_vTlo);
    cudaGetSymbolAddress((void**)&atthi, g_atthi);
    cudaGetSymbolAddress((void**)&attlo, g_attlo);
    cudaGetSymbolAddress((void**)&k,     g_k);
    cudaGetSymbolAddress((void**)&v,     g_v);
    cudaGetSymbolAddress((void**)&score, g_score);
    cudaGetSymbolAddress((void**)&part,  g_part);

    cudaFuncSetAttribute(qkv_kernel,
                         cudaFuncAttributeMaxDynamicSharedMemorySize, GEMM_SMEM_BYTES);
    cudaFuncSetAttribute(mma_bf16_kernel<false, false>,
                         cudaFuncAttributeMaxDynamicSharedMemorySize, GEMM_SMEM_BYTES);
    cudaFuncSetAttribute(ctx_kernel,
                         cudaFuncAttributeMaxDynamicSharedMemorySize, GEMM_SMEM_BYTES);

    const float inv_sqrt_d = 1.0f / sqrtf((float)DDIM);
    const dim3 tb(32, 8);

    // Pre-split x; transpose+split weights W [in,out] -> WT [out,in] (bf16 hi/lo)
    split_kernel<<<(N_TOK * DDIM) / 256, 256>>>(x, xhi, xlo);
    transpose_split_kernel<<<dim3(DDIM / 32, DDIM / 32), tb>>>(Wq, WThi + 0 * DDIM * DDIM, WTlo + 0 * DDIM * DDIM, DDIM, DDIM);
    transpose_split_kernel<<<dim3(DDIM / 32, DDIM / 32), tb>>>(Wk, WThi + 1 * DDIM * DDIM, WTlo + 1 * DDIM * DDIM, DDIM, DDIM);
    transpose_split_kernel<<<dim3(DDIM / 32, DDIM / 32), tb>>>(Wv, WThi + 2 * DDIM * DDIM, WTlo + 2 * DDIM * DDIM, DDIM, DDIM);

    // QKV merged: grid (4, 32, 3)
    qkv_kernel<<<dim3(DDIM / 128, N_TOK / 128, 3), 512, GEMM_SMEM_BYTES>>>(
        xhi, xlo, WThi, WTlo, bq, bk, bv, qhi, qlo, k, v);

    // kT[n][dd] = (k viewed as [512][4096])^T, split; vT = v^T, split
    transpose_split_kernel<<<dim3(N_TOK / 32, DDIM / 32), tb>>>(k, kThi, kTlo, DDIM, N_TOK);
    transpose_split_kernel<<<dim3(DDIM / 32, N_TOK / 32), tb>>>(v, vThi, vTlo, N_TOK, DDIM);

    // Score: M=N=4096, K=512
    mma_bf16_kernel<false, false><<<dim3(N_TOK / 128, N_TOK / 128), 512, GEMM_SMEM_BYTES>>>(
        qhi, qlo, DDIM, kThi, kTlo, DDIM, score, nullptr, nullptr, N_TOK,
        DDIM, nullptr, inv_sqrt_d);

    // Exact top-k + masked softmax; attn emitted pre-split (bf16)
    topk_softmax_kernel<<<N_TOK, 512>>>(score, atthi, attlo);

    // Context: merged split-K=4, grid (4, 32, 4), then deterministic reduce
    ctx_kernel<<<dim3(DDIM / 128, N_TOK / 128, 4), 512, GEMM_SMEM_BYTES>>>(
        atthi, attlo, vThi, vTlo, part);
    reduce4_kernel<<<(N_TOK * DDIM / 4) / 256, 256>>>(
        (const float4*)(part + 0 * (size_t)N_TOK * DDIM),
        (const float4*)(part + 1 * (size_t)N_TOK * DDIM),
        (const float4*)(part + 2 * (size_t)N_TOK * DDIM),
        (const float4*)(part + 3 * (size_t)N_TOK * DDIM),
        (float4*)out);
}